// round 9
// baseline (speedup 1.0000x reference)
#include <cuda_runtime.h>
#include <cuda_bf16.h>
#include <cstdint>

#define BATCH 2
#define CH    128
#define NTOK  4096

// ---------------- scratch (device .bss — no allocation) ----------------
__device__ __nv_bfloat16 g_qh[BATCH][NTOK][CH];
__device__ __nv_bfloat16 g_ql[BATCH][NTOK][CH];
__device__ __nv_bfloat16 g_kh[BATCH][NTOK][CH];
__device__ __nv_bfloat16 g_kl[BATCH][NTOK][CH];
__device__ __nv_bfloat16 g_v [BATCH][CH][NTOK];
__device__ float         g_S [BATCH][NTOK][NTOK];
__device__ __nv_bfloat16 g_P [BATCH][NTOK][NTOK];
__device__ float         g_O [BATCH][4][NTOK][CH];

// ---------------- mma helpers ----------------
__device__ __forceinline__ void ldsm4(uint32_t r[4], const void* p) {
    uint32_t a = (uint32_t)__cvta_generic_to_shared(p);
    asm volatile("ldmatrix.sync.aligned.m8n8.x4.shared.b16 {%0,%1,%2,%3}, [%4];\n"
                 : "=r"(r[0]), "=r"(r[1]), "=r"(r[2]), "=r"(r[3]) : "r"(a));
}
__device__ __forceinline__ void mma_bf16(float c[4], const uint32_t a[4], const uint32_t b0, const uint32_t b1) {
    asm volatile("mma.sync.aligned.m16n8k16.row.col.f32.bf16.bf16.f32 "
                 "{%0,%1,%2,%3},{%4,%5,%6,%7},{%8,%9},{%0,%1,%2,%3};\n"
                 : "+f"(c[0]), "+f"(c[1]), "+f"(c[2]), "+f"(c[3])
                 : "r"(a[0]), "r"(a[1]), "r"(a[2]), "r"(a[3]), "r"(b0), "r"(b1));
}
// 128-row x 64-col bf16 tile -> smem[128][72]
__device__ __forceinline__ void load_tile(__nv_bfloat16 (*sm)[72],
                                          const __nv_bfloat16* __restrict__ src,
                                          int row0, int col0, int ld, int t) {
    const __nv_bfloat16* s = src + (size_t)row0 * ld + col0;
    #pragma unroll
    for (int i = t; i < 128 * 8; i += 256) {
        int r = i >> 3, u = i & 7;
        *(uint4*)&sm[r][u * 8] = *(const uint4*)(s + (size_t)r * ld + u * 8);
    }
}

// ---------------- K1: QKV projection (fp32) + bf16 hi/lo split ----------------
__global__ __launch_bounds__(256) void k1_proj(
    const float* __restrict__ x,
    const float* __restrict__ Wq, const float* __restrict__ bq,
    const float* __restrict__ Wk, const float* __restrict__ bk,
    const float* __restrict__ Wv, const float* __restrict__ bv)
{
    const int n0  = blockIdx.x * 128;
    const int mat = blockIdx.y;
    const int b   = blockIdx.z;
    const float* W    = (mat == 0) ? Wq : (mat == 1) ? Wk : Wv;
    const float* bias = (mat == 0) ? bq : (mat == 1) ? bk : bv;

    __shared__ float sW[32][132];
    __shared__ float sX[32][128];

    const int t  = threadIdx.x;
    const int n4 = (t & 31) * 4;
    const int ob = (t >> 5) * 16;

    float acc[16][4];
    #pragma unroll
    for (int i = 0; i < 16; i++)
        #pragma unroll
        for (int j = 0; j < 4; j++) acc[i][j] = 0.f;

    const float* xb = x + (size_t)b * CH * NTOK;

    for (int c0 = 0; c0 < 128; c0 += 32) {
        __syncthreads();
        for (int i = t; i < 128 * 8; i += 256) {
            int o = i >> 3, u = i & 7;
            float4 w4 = *(const float4*)(W + o * 128 + c0 + u * 4);
            sW[u * 4 + 0][o] = w4.x; sW[u * 4 + 1][o] = w4.y;
            sW[u * 4 + 2][o] = w4.z; sW[u * 4 + 3][o] = w4.w;
        }
        for (int i = t; i < 32 * 32; i += 256) {
            int r = i >> 5, u = i & 31;
            *(float4*)&sX[r][u * 4] = *(const float4*)(xb + (size_t)(c0 + r) * NTOK + n0 + u * 4);
        }
        __syncthreads();
        #pragma unroll
        for (int c = 0; c < 32; c++) {
            float4 xv = *(float4*)&sX[c][n4];
            #pragma unroll
            for (int iq = 0; iq < 4; iq++) {
                float4 wv = *(float4*)&sW[c][ob + iq * 4];
                float wr[4] = {wv.x, wv.y, wv.z, wv.w};
                #pragma unroll
                for (int jj = 0; jj < 4; jj++) {
                    acc[iq * 4 + jj][0] += wr[jj] * xv.x;
                    acc[iq * 4 + jj][1] += wr[jj] * xv.y;
                    acc[iq * 4 + jj][2] += wr[jj] * xv.z;
                    acc[iq * 4 + jj][3] += wr[jj] * xv.w;
                }
            }
        }
    }

    float bi[16];
    #pragma unroll
    for (int i = 0; i < 16; i++) bi[i] = bias[ob + i];

    if (mat == 2) {
        #pragma unroll
        for (int i = 0; i < 16; i++) {
            __align__(8) __nv_bfloat16 h[4];
            #pragma unroll
            for (int j = 0; j < 4; j++) h[j] = __float2bfloat16(acc[i][j] + bi[i]);
            *(uint2*)&g_v[b][ob + i][n0 + n4] = *(uint2*)h;
        }
    } else {
        __nv_bfloat16 (*dh)[NTOK][CH] = (mat == 0) ? g_qh : g_kh;
        __nv_bfloat16 (*dl)[NTOK][CH] = (mat == 0) ? g_ql : g_kl;
        #pragma unroll
        for (int j = 0; j < 4; j++) {
            __align__(16) __nv_bfloat16 hh[16];
            __align__(16) __nv_bfloat16 ll[16];
            #pragma unroll
            for (int i = 0; i < 16; i++) {
                float v = acc[i][j] + bi[i];
                __nv_bfloat16 h = __float2bfloat16(v);
                hh[i] = h;
                ll[i] = __float2bfloat16(v - __bfloat162float(h));
            }
            int n = n0 + n4 + j;
            *(uint4*)&dh[b][n][ob + 0] = *(uint4*)&hh[0];
            *(uint4*)&dh[b][n][ob + 8] = *(uint4*)&hh[8];
            *(uint4*)&dl[b][n][ob + 0] = *(uint4*)&ll[0];
            *(uint4*)&dl[b][n][ob + 8] = *(uint4*)&ll[8];
        }
    }
}

// ---------------- K2: S = 1.3*(qh·kh + qh·kl + ql·kh), bf16x3 MMA ----------------
__global__ __launch_bounds__(256, 2) void k2_logits() {
    const int n0 = blockIdx.x * 128;
    const int m0 = blockIdx.y * 128;
    const int b  = blockIdx.z;

    __shared__ __align__(16) __nv_bfloat16 sA[128][72];
    __shared__ __align__(16) __nv_bfloat16 sB[128][72];

    const int t  = threadIdx.x, wid = t >> 5, ln = t & 31;
    const int wm = (wid >> 2) * 64;
    const int wn = (wid & 3) * 32;

    float acc[4][4][4] = {};

    const __nv_bfloat16* aSrc[3] = { &g_qh[b][0][0], &g_qh[b][0][0], &g_ql[b][0][0] };
    const __nv_bfloat16* bSrc[3] = { &g_kh[b][0][0], &g_kl[b][0][0], &g_kh[b][0][0] };

    for (int seg = 0; seg < 3; seg++)
    for (int half = 0; half < 2; half++) {
        __syncthreads();
        load_tile(sA, aSrc[seg], n0, half * 64, CH, t);
        load_tile(sB, bSrc[seg], m0, half * 64, CH, t);
        __syncthreads();
        #pragma unroll
        for (int ks = 0; ks < 4; ks++) {
            const int kk = ks * 16;
            uint32_t a[4][4], bb[2][4];
            #pragma unroll
            for (int mi = 0; mi < 4; mi++)
                ldsm4(a[mi], &sA[wm + mi * 16 + (ln & 15)][kk + (ln >> 4) * 8]);
            #pragma unroll
            for (int nh = 0; nh < 2; nh++)
                ldsm4(bb[nh], &sB[wn + nh * 16 + (ln & 7) + ((ln >> 4) << 3)]
                                 [kk + (((ln >> 3) & 1) << 3)]);
            #pragma unroll
            for (int mi = 0; mi < 4; mi++)
                #pragma unroll
                for (int ni = 0; ni < 4; ni++)
                    mma_bf16(acc[mi][ni], a[mi],
                             bb[ni >> 1][(ni & 1) * 2], bb[ni >> 1][(ni & 1) * 2 + 1]);
        }
    }

    float* Sb = &g_S[b][0][0];
    #pragma unroll
    for (int mi = 0; mi < 4; mi++) {
        int r = n0 + wm + mi * 16 + (ln >> 2);
        #pragma unroll
        for (int ni = 0; ni < 4; ni++) {
            int c = m0 + wn + ni * 8 + (ln & 3) * 2;
            *(float2*)(Sb + (size_t)r * NTOK + c) =
                make_float2(1.3f * acc[mi][ni][0], 1.3f * acc[mi][ni][1]);
            *(float2*)(Sb + (size_t)(r + 8) * NTOK + c) =
                make_float2(1.3f * acc[mi][ni][2], 1.3f * acc[mi][ni][3]);
        }
    }
}

// ---------------- K3: row softmax (fp32 exact) -> P bf16 ----------------
__global__ __launch_bounds__(256) void k3_softmax() {
    const int n = blockIdx.x, b = blockIdx.y;
    const float* row = &g_S[b][n][0];
    __nv_bfloat16* prow = &g_P[b][n][0];
    const int t = threadIdx.x;
    __shared__ float red[8];

    float4 vv[4];
    float mx = -1e30f;
    #pragma unroll
    for (int j = 0; j < 4; j++) {
        vv[j] = *(const float4*)(row + (t + 256 * j) * 4);
        mx = fmaxf(mx, fmaxf(fmaxf(vv[j].x, vv[j].y), fmaxf(vv[j].z, vv[j].w)));
    }
    #pragma unroll
    for (int o = 16; o; o >>= 1) mx = fmaxf(mx, __shfl_xor_sync(0xffffffffu, mx, o));
    if ((t & 31) == 0) red[t >> 5] = mx;
    __syncthreads();
    mx = red[0];
    #pragma unroll
    for (int i = 1; i < 8; i++) mx = fmaxf(mx, red[i]);

    float s = 0.f;
    #pragma unroll
    for (int j = 0; j < 4; j++) {
        vv[j].x = __expf(vv[j].x - mx); vv[j].y = __expf(vv[j].y - mx);
        vv[j].z = __expf(vv[j].z - mx); vv[j].w = __expf(vv[j].w - mx);
        s += (vv[j].x + vv[j].y) + (vv[j].z + vv[j].w);
    }
    #pragma unroll
    for (int o = 16; o; o >>= 1) s += __shfl_xor_sync(0xffffffffu, s, o);
    __syncthreads();
    if ((t & 31) == 0) red[t >> 5] = s;
    __syncthreads();
    s = 0.f;
    #pragma unroll
    for (int i = 0; i < 8; i++) s += red[i];

    const float inv = 1.0f / s;
    #pragma unroll
    for (int j = 0; j < 4; j++) {
        __align__(8) __nv_bfloat16 p[4];
        p[0] = __float2bfloat16(vv[j].x * inv); p[1] = __float2bfloat16(vv[j].y * inv);
        p[2] = __float2bfloat16(vv[j].z * inv); p[3] = __float2bfloat16(vv[j].w * inv);
        *(uint2*)(prow + (t + 256 * j) * 4) = *(uint2*)p;
    }
}

// ---------------- K4: O_part[n][c] = P · V^T (split-K over m) ----------------
__global__ __launch_bounds__(256, 2) void k4_pv() {
    const int n0    = blockIdx.x * 128;
    const int chunk = blockIdx.y;
    const int b     = blockIdx.z;

    __shared__ __align__(16) __nv_bfloat16 sA[128][72];
    __shared__ __align__(16) __nv_bfloat16 sB[128][72];

    const int t  = threadIdx.x, wid = t >> 5, ln = t & 31;
    const int wm = (wid >> 2) * 64;
    const int wn = (wid & 3) * 32;

    float acc[4][4][4] = {};
    const __nv_bfloat16* P = &g_P[b][0][0];
    const __nv_bfloat16* V = &g_v[b][0][0];

    for (int kt = 0; kt < 16; kt++) {
        const int col0 = chunk * 1024 + kt * 64;
        __syncthreads();
        load_tile(sA, P, n0, col0, NTOK, t);
        load_tile(sB, V, 0,  col0, NTOK, t);
        __syncthreads();
        #pragma unroll
        for (int ks = 0; ks < 4; ks++) {
            const int kk = ks * 16;
            uint32_t a[4][4], bb[2][4];
            #pragma unroll
            for (int mi = 0; mi < 4; mi++)
                ldsm4(a[mi], &sA[wm + mi * 16 + (ln & 15)][kk + (ln >> 4) * 8]);
            #pragma unroll
            for (int nh = 0; nh < 2; nh++)
                ldsm4(bb[nh], &sB[wn + nh * 16 + (ln & 7) + ((ln >> 4) << 3)]
                                 [kk + (((ln >> 3) & 1) << 3)]);
            #pragma unroll
            for (int mi = 0; mi < 4; mi++)
                #pragma unroll
                for (int ni = 0; ni < 4; ni++)
                    mma_bf16(acc[mi][ni], a[mi],
                             bb[ni >> 1][(ni & 1) * 2], bb[ni >> 1][(ni & 1) * 2 + 1]);
        }
    }

    float* Ob = &g_O[b][chunk][0][0];
    #pragma unroll
    for (int mi = 0; mi < 4; mi++) {
        int r = n0 + wm + mi * 16 + (ln >> 2);
        #pragma unroll
        for (int ni = 0; ni < 4; ni++) {
            int c = wn + ni * 8 + (ln & 3) * 2;
            *(float2*)(Ob + (size_t)r * CH + c)       = make_float2(acc[mi][ni][0], acc[mi][ni][1]);
            *(float2*)(Ob + (size_t)(r + 8) * CH + c) = make_float2(acc[mi][ni][2], acc[mi][ni][3]);
        }
    }
}

// ---------------- K5: reduce split-K, transpose, residual ----------------
__global__ __launch_bounds__(256) void k5_reduce(
    const float* __restrict__ x, const float* __restrict__ gamma,
    float* __restrict__ out)
{
    const int n0 = blockIdx.x * 32;
    const int b  = blockIdx.y;
    const int t  = threadIdx.x;
    const float g = *gamma;

    __shared__ float s[128][33];

    for (int i = t; i < 32 * 128; i += 256) {
        int nl = i >> 7, c = i & 127;
        float acc = 0.f;
        #pragma unroll
        for (int ch = 0; ch < 4; ch++)
            acc += g_O[b][ch][n0 + nl][c];
        s[c][nl] = acc;
    }
    __syncthreads();
    const size_t base = (size_t)b * CH * NTOK;
    for (int i = t; i < 128 * 32; i += 256) {
        int c = i >> 5, nl = i & 31;
        size_t idx = base + (size_t)c * NTOK + n0 + nl;
        out[idx] = x[idx] + g * s[c][nl];
    }
}

extern "C" void kernel_launch(void* const* d_in, const int* in_sizes, int n_in,
                              void* d_out, int out_size) {
    const float* x  = (const float*)d_in[0];
    const float* Wq = (const float*)d_in[1];
    const float* bq = (const float*)d_in[2];
    const float* Wk = (const float*)d_in[3];
    const float* bk = (const float*)d_in[4];
    const float* Wv = (const float*)d_in[5];
    const float* bv = (const float*)d_in[6];
    const float* gm = (const float*)d_in[7];
    float* out = (float*)d_out;

    k1_proj   <<<dim3(NTOK / 128, 3, BATCH),      256>>>(x, Wq, bq, Wk, bk, Wv, bv);
    k2_logits <<<dim3(NTOK / 128, NTOK / 128, BATCH), 256>>>();
    k3_softmax<<<dim3(NTOK, BATCH),               256>>>();
    k4_pv     <<<dim3(NTOK / 128, 4, BATCH),      256>>>();
    k5_reduce <<<dim3(NTOK / 32, BATCH),          256>>>(x, gm, out);
}

// round 11
// speedup vs baseline: 1.3914x; 1.3914x over previous
#include <cuda_runtime.h>
#include <cuda_bf16.h>
#include <cstdint>

#define BATCH 2
#define CH    128
#define NTOK  4096
#define KT    64        // kv tokens per inner tile
#define HALF_M 2048     // kv tokens per split-K half
#define NTILES 32       // inner tiles per half

// ---------------- scratch (device .bss — no allocation) ----------------
__device__ __nv_bfloat16 g_qh[BATCH][NTOK][CH];
__device__ __nv_bfloat16 g_ql[BATCH][NTOK][CH];
__device__ __nv_bfloat16 g_kh[BATCH][NTOK][CH];
__device__ __nv_bfloat16 g_kl[BATCH][NTOK][CH];
__device__ __nv_bfloat16 g_v [BATCH][CH][NTOK];
__device__ float g_O [BATCH][2][NTOK][CH];   // unnormalized partial O
__device__ float g_ms[BATCH][2][NTOK];       // row max (of 1.3*s)
__device__ float g_ls[BATCH][2][NTOK];       // row sum

// ---------------- smem for fused attention ----------------
struct SmemT {
    __nv_bfloat16 kh[2][64][136];   // [stage][m][c]  64 tok x 128 ch (+8 pad)
    __nv_bfloat16 kl[2][64][136];
    __nv_bfloat16 v [2][128][72];   // [stage][c][m]  128 ch x 64 tok (+8 pad)
};

// ---------------- helpers ----------------
__device__ __forceinline__ void ldsm4(uint32_t r[4], const void* p) {
    uint32_t a = (uint32_t)__cvta_generic_to_shared(p);
    asm volatile("ldmatrix.sync.aligned.m8n8.x4.shared.b16 {%0,%1,%2,%3}, [%4];\n"
                 : "=r"(r[0]), "=r"(r[1]), "=r"(r[2]), "=r"(r[3]) : "r"(a));
}
__device__ __forceinline__ void mma_bf16(float c[4], const uint32_t a[4], uint32_t b0, uint32_t b1) {
    asm volatile("mma.sync.aligned.m16n8k16.row.col.f32.bf16.bf16.f32 "
                 "{%0,%1,%2,%3},{%4,%5,%6,%7},{%8,%9},{%0,%1,%2,%3};\n"
                 : "+f"(c[0]), "+f"(c[1]), "+f"(c[2]), "+f"(c[3])
                 : "r"(a[0]), "r"(a[1]), "r"(a[2]), "r"(a[3]), "r"(b0), "r"(b1));
}
__device__ __forceinline__ void cpa16(void* dst, const void* src) {
    uint32_t d = (uint32_t)__cvta_generic_to_shared(dst);
    asm volatile("cp.async.cg.shared.global [%0], [%1], 16;\n" :: "r"(d), "l"(src));
}
#define CP_COMMIT() asm volatile("cp.async.commit_group;\n")
#define CP_WAIT(n)  asm volatile("cp.async.wait_group %0;\n" :: "n"(n))

// 3072 x 16B chunks: kh 1024 (64 rows x 16 chunks), kl 1024, v 1024 (128 rows x 8)
__device__ __forceinline__ void issue_tile(SmemT* sm, int b, int half, int tt, int st, int tid) {
    const int m0 = half * HALF_M + tt * KT;
    #pragma unroll
    for (int i = tid; i < 3072; i += 256) {
        if (i < 1024) {
            int r = i >> 4, ch = i & 15;
            cpa16(&sm->kh[st][r][ch * 8], &g_kh[b][m0 + r][ch * 8]);
        } else if (i < 2048) {
            int j = i - 1024, r = j >> 4, ch = j & 15;
            cpa16(&sm->kl[st][r][ch * 8], &g_kl[b][m0 + r][ch * 8]);
        } else {
            int j = i - 2048, r = j >> 3, ch = j & 7;
            cpa16(&sm->v[st][r][ch * 8], &g_v[b][r][m0 + ch * 8]);
        }
    }
}

// ---------------- K1: QKV projection (fp32) + bf16 hi/lo split ----------------
__global__ __launch_bounds__(256) void k1_proj(
    const float* __restrict__ x,
    const float* __restrict__ Wq, const float* __restrict__ bq,
    const float* __restrict__ Wk, const float* __restrict__ bk,
    const float* __restrict__ Wv, const float* __restrict__ bv)
{
    const int n0  = blockIdx.x * 128;
    const int mat = blockIdx.y;
    const int b   = blockIdx.z;
    const float* W    = (mat == 0) ? Wq : (mat == 1) ? Wk : Wv;
    const float* bias = (mat == 0) ? bq : (mat == 1) ? bk : bv;

    __shared__ float sW[32][132];
    __shared__ float sX[32][128];

    const int t  = threadIdx.x;
    const int n4 = (t & 31) * 4;
    const int ob = (t >> 5) * 16;

    float acc[16][4];
    #pragma unroll
    for (int i = 0; i < 16; i++)
        #pragma unroll
        for (int j = 0; j < 4; j++) acc[i][j] = 0.f;

    const float* xb = x + (size_t)b * CH * NTOK;

    for (int c0 = 0; c0 < 128; c0 += 32) {
        __syncthreads();
        for (int i = t; i < 128 * 8; i += 256) {
            int o = i >> 3, u = i & 7;
            float4 w4 = *(const float4*)(W + o * 128 + c0 + u * 4);
            sW[u * 4 + 0][o] = w4.x; sW[u * 4 + 1][o] = w4.y;
            sW[u * 4 + 2][o] = w4.z; sW[u * 4 + 3][o] = w4.w;
        }
        for (int i = t; i < 32 * 32; i += 256) {
            int r = i >> 5, u = i & 31;
            *(float4*)&sX[r][u * 4] = *(const float4*)(xb + (size_t)(c0 + r) * NTOK + n0 + u * 4);
        }
        __syncthreads();
        #pragma unroll
        for (int c = 0; c < 32; c++) {
            float4 xv = *(float4*)&sX[c][n4];
            #pragma unroll
            for (int iq = 0; iq < 4; iq++) {
                float4 wv = *(float4*)&sW[c][ob + iq * 4];
                float wr[4] = {wv.x, wv.y, wv.z, wv.w};
                #pragma unroll
                for (int jj = 0; jj < 4; jj++) {
                    acc[iq * 4 + jj][0] += wr[jj] * xv.x;
                    acc[iq * 4 + jj][1] += wr[jj] * xv.y;
                    acc[iq * 4 + jj][2] += wr[jj] * xv.z;
                    acc[iq * 4 + jj][3] += wr[jj] * xv.w;
                }
            }
        }
    }

    float bi[16];
    #pragma unroll
    for (int i = 0; i < 16; i++) bi[i] = bias[ob + i];

    if (mat == 2) {
        #pragma unroll
        for (int i = 0; i < 16; i++) {
            __align__(8) __nv_bfloat16 h[4];
            #pragma unroll
            for (int j = 0; j < 4; j++) h[j] = __float2bfloat16(acc[i][j] + bi[i]);
            *(uint2*)&g_v[b][ob + i][n0 + n4] = *(uint2*)h;
        }
    } else {
        __nv_bfloat16 (*dh)[NTOK][CH] = (mat == 0) ? g_qh : g_kh;
        __nv_bfloat16 (*dl)[NTOK][CH] = (mat == 0) ? g_ql : g_kl;
        #pragma unroll
        for (int j = 0; j < 4; j++) {
            __align__(16) __nv_bfloat16 hh[16];
            __align__(16) __nv_bfloat16 ll[16];
            #pragma unroll
            for (int i = 0; i < 16; i++) {
                float v = acc[i][j] + bi[i];
                __nv_bfloat16 h = __float2bfloat16(v);
                hh[i] = h;
                ll[i] = __float2bfloat16(v - __bfloat162float(h));
            }
            int n = n0 + n4 + j;
            *(uint4*)&dh[b][n][ob + 0] = *(uint4*)&hh[0];
            *(uint4*)&dh[b][n][ob + 8] = *(uint4*)&hh[8];
            *(uint4*)&dl[b][n][ob + 0] = *(uint4*)&ll[0];
            *(uint4*)&dl[b][n][ob + 8] = *(uint4*)&ll[8];
        }
    }
}

// ---------------- K2: fused flash attention (split-K=2 over kv) ----------------
__global__ __launch_bounds__(256, 1) void k2_attn() {
    extern __shared__ char smem_raw[];
    SmemT* sm = (SmemT*)smem_raw;

    const int n0   = blockIdx.x * 128;
    const int half = blockIdx.y;
    const int b    = blockIdx.z;
    const int t    = threadIdx.x, wid = t >> 5, ln = t & 31;

    // ---- load Q fragments (hi/lo) into registers, staged through smem ----
    uint32_t qh[8][4], ql[8][4];
    for (int round = 0; round < 2; round++) {
        for (int i = t; i < 1024; i += 256) {
            int r = i >> 4, ch = i & 15;
            *(uint4*)&sm->kh[0][r][ch * 8] = *(const uint4*)&g_qh[b][n0 + round * 64 + r][ch * 8];
            *(uint4*)&sm->kl[0][r][ch * 8] = *(const uint4*)&g_ql[b][n0 + round * 64 + r][ch * 8];
        }
        __syncthreads();
        if ((wid >> 2) == round) {
            int wl = (wid & 3) * 16;
            #pragma unroll
            for (int ks = 0; ks < 8; ks++) {
                ldsm4(qh[ks], &sm->kh[0][wl + (ln & 15)][ks * 16 + (ln >> 4) * 8]);
                ldsm4(ql[ks], &sm->kl[0][wl + (ln & 15)][ks * 16 + (ln >> 4) * 8]);
            }
        }
        __syncthreads();
    }

    float o[16][4];
    #pragma unroll
    for (int i = 0; i < 16; i++)
        #pragma unroll
        for (int j = 0; j < 4; j++) o[i][j] = 0.f;
    float rm0 = -1e30f, rm1 = -1e30f, rl0 = 0.f, rl1 = 0.f;

    issue_tile(sm, b, half, 0, 0, t);
    CP_COMMIT();

    for (int tt = 0; tt < NTILES; tt++) {
        const int st = tt & 1;
        if (tt + 1 < NTILES) {
            issue_tile(sm, b, half, tt + 1, (tt + 1) & 1, t);
            CP_COMMIT();
            CP_WAIT(1);
        } else {
            CP_WAIT(0);
        }
        __syncthreads();

        // ---- S = 1.3*(qh·kh + qh·kl + ql·kh) : 16 rows x 64 m per warp ----
        float s[8][4];
        #pragma unroll
        for (int i = 0; i < 8; i++)
            #pragma unroll
            for (int j = 0; j < 4; j++) s[i][j] = 0.f;

        #pragma unroll
        for (int ks = 0; ks < 8; ks++) {
            const int kk = ks * 16;
            uint32_t bh[4][4], bl[4][4];
            #pragma unroll
            for (int g = 0; g < 4; g++) {
                int rr = g * 16 + (ln & 7) + ((ln >> 4) << 3);
                int cc = kk + (((ln >> 3) & 1) << 3);
                ldsm4(bh[g], &sm->kh[st][rr][cc]);
                ldsm4(bl[g], &sm->kl[st][rr][cc]);
            }
            #pragma unroll
            for (int g = 0; g < 4; g++)
                #pragma unroll
                for (int j = 0; j < 2; j++) {
                    const int ni = g * 2 + j;
                    mma_bf16(s[ni], qh[ks], bh[g][j * 2], bh[g][j * 2 + 1]);
                    mma_bf16(s[ni], qh[ks], bl[g][j * 2], bl[g][j * 2 + 1]);
                    mma_bf16(s[ni], ql[ks], bh[g][j * 2], bh[g][j * 2 + 1]);
                }
        }

        // ---- online softmax (rows fully warp-owned; quad-lane reductions) ----
        #pragma unroll
        for (int i = 0; i < 8; i++)
            #pragma unroll
            for (int j = 0; j < 4; j++) s[i][j] *= 1.3f;

        float tm0 = -1e30f, tm1 = -1e30f;
        #pragma unroll
        for (int i = 0; i < 8; i++) {
            tm0 = fmaxf(tm0, fmaxf(s[i][0], s[i][1]));
            tm1 = fmaxf(tm1, fmaxf(s[i][2], s[i][3]));
        }
        tm0 = fmaxf(tm0, __shfl_xor_sync(0xffffffffu, tm0, 1));
        tm0 = fmaxf(tm0, __shfl_xor_sync(0xffffffffu, tm0, 2));
        tm1 = fmaxf(tm1, __shfl_xor_sync(0xffffffffu, tm1, 1));
        tm1 = fmaxf(tm1, __shfl_xor_sync(0xffffffffu, tm1, 2));

        const float mn0 = fmaxf(rm0, tm0), mn1 = fmaxf(rm1, tm1);
        const float sc0 = __expf(rm0 - mn0), sc1 = __expf(rm1 - mn1);
        rm0 = mn0; rm1 = mn1;

        float ts0 = 0.f, ts1 = 0.f;
        #pragma unroll
        for (int i = 0; i < 8; i++) {
            s[i][0] = __expf(s[i][0] - mn0);
            s[i][1] = __expf(s[i][1] - mn0);
            s[i][2] = __expf(s[i][2] - mn1);
            s[i][3] = __expf(s[i][3] - mn1);
            ts0 += s[i][0] + s[i][1];
            ts1 += s[i][2] + s[i][3];
        }
        ts0 += __shfl_xor_sync(0xffffffffu, ts0, 1);
        ts0 += __shfl_xor_sync(0xffffffffu, ts0, 2);
        ts1 += __shfl_xor_sync(0xffffffffu, ts1, 1);
        ts1 += __shfl_xor_sync(0xffffffffu, ts1, 2);
        rl0 = rl0 * sc0 + ts0;
        rl1 = rl1 * sc1 + ts1;

        #pragma unroll
        for (int i = 0; i < 16; i++) {
            o[i][0] *= sc0; o[i][1] *= sc0;
            o[i][2] *= sc1; o[i][3] *= sc1;
        }

        // ---- repack P (C-frag -> A-frag) ----
        uint32_t pf[4][4];
        #pragma unroll
        for (int kp = 0; kp < 4; kp++) {
            __nv_bfloat162 h;
            h = __floats2bfloat162_rn(s[2*kp][0],   s[2*kp][1]);   pf[kp][0] = *(uint32_t*)&h;
            h = __floats2bfloat162_rn(s[2*kp][2],   s[2*kp][3]);   pf[kp][1] = *(uint32_t*)&h;
            h = __floats2bfloat162_rn(s[2*kp+1][0], s[2*kp+1][1]); pf[kp][2] = *(uint32_t*)&h;
            h = __floats2bfloat162_rn(s[2*kp+1][2], s[2*kp+1][3]); pf[kp][3] = *(uint32_t*)&h;
        }

        // ---- O += P · V^T ----
        #pragma unroll
        for (int kp = 0; kp < 4; kp++) {
            #pragma unroll
            for (int cg = 0; cg < 8; cg++) {
                uint32_t vb[4];
                ldsm4(vb, &sm->v[st][cg * 16 + (ln & 7) + ((ln >> 4) << 3)]
                                    [kp * 16 + (((ln >> 3) & 1) << 3)]);
                mma_bf16(o[cg * 2],     pf[kp], vb[0], vb[1]);
                mma_bf16(o[cg * 2 + 1], pf[kp], vb[2], vb[3]);
            }
        }
        __syncthreads();
    }

    // ---- epilogue: unnormalized O + row stats ----
    const int gr = ln >> 2;
    const int r0 = n0 + wid * 16 + gr, r1 = r0 + 8;
    float* O0 = &g_O[b][half][0][0];
    #pragma unroll
    for (int ni = 0; ni < 16; ni++) {
        int c = ni * 8 + (ln & 3) * 2;
        *(float2*)(O0 + (size_t)r0 * CH + c) = make_float2(o[ni][0], o[ni][1]);
        *(float2*)(O0 + (size_t)r1 * CH + c) = make_float2(o[ni][2], o[ni][3]);
    }
    if ((ln & 3) == 0) {
        g_ms[b][half][r0] = rm0; g_ls[b][half][r0] = rl0;
        g_ms[b][half][r1] = rm1; g_ls[b][half][r1] = rl1;
    }
}

// ---------------- K5: LSE combine, transpose, residual ----------------
__global__ __launch_bounds__(256) void k5_reduce(
    const float* __restrict__ x, const float* __restrict__ gamma,
    float* __restrict__ out)
{
    const int n0 = blockIdx.x * 32;
    const int b  = blockIdx.y;
    const int t  = threadIdx.x;
    const float g = *gamma;

    __shared__ float s[128][33];
    __shared__ float f0[32], f1[32];

    if (t < 32) {
        int n = n0 + t;
        float m1 = g_ms[b][0][n], l1 = g_ls[b][0][n];
        float m2 = g_ms[b][1][n], l2 = g_ls[b][1][n];
        float M  = fmaxf(m1, m2);
        float w1 = __expf(m1 - M), w2 = __expf(m2 - M);
        float inv = 1.0f / (w1 * l1 + w2 * l2);
        f0[t] = w1 * inv; f1[t] = w2 * inv;
    }
    __syncthreads();

    for (int i = t; i < 32 * 128; i += 256) {
        int nl = i >> 7, c = i & 127;
        s[c][nl] = f0[nl] * g_O[b][0][n0 + nl][c] + f1[nl] * g_O[b][1][n0 + nl][c];
    }
    __syncthreads();
    const size_t base = (size_t)b * CH * NTOK;
    for (int i = t; i < 128 * 32; i += 256) {
        int c = i >> 5, nl = i & 31;
        size_t idx = base + (size_t)c * NTOK + n0 + nl;
        out[idx] = x[idx] + g * s[c][nl];
    }
}

extern "C" void kernel_launch(void* const* d_in, const int* in_sizes, int n_in,
                              void* d_out, int out_size) {
    const float* x  = (const float*)d_in[0];
    const float* Wq = (const float*)d_in[1];
    const float* bq = (const float*)d_in[2];
    const float* Wk = (const float*)d_in[3];
    const float* bk = (const float*)d_in[4];
    const float* Wv = (const float*)d_in[5];
    const float* bv = (const float*)d_in[6];
    const float* gm = (const float*)d_in[7];
    float* out = (float*)d_out;

    cudaFuncSetAttribute(k2_attn, cudaFuncAttributeMaxDynamicSharedMemorySize,
                         (int)sizeof(SmemT));

    k1_proj  <<<dim3(NTOK / 128, 3, BATCH), 256>>>(x, Wq, bq, Wk, bk, Wv, bv);
    k2_attn  <<<dim3(NTOK / 128, 2, BATCH), 256, sizeof(SmemT)>>>();
    k5_reduce<<<dim3(NTOK / 32, BATCH),     256>>>(x, gm, out);
}

// round 12
// speedup vs baseline: 1.4124x; 1.0151x over previous
#include <cuda_runtime.h>
#include <cuda_bf16.h>
#include <cstdint>

#define BATCH 2
#define CH    128
#define NTOK  4096
#define KT    64        // kv tokens per inner tile
#define HALF_M 2048     // kv tokens per split-K half
#define NTILES 32       // inner tiles per half

// ---------------- scratch (device .bss — no allocation) ----------------
__device__ __nv_bfloat16 g_qh[BATCH][NTOK][CH];
__device__ __nv_bfloat16 g_ql[BATCH][NTOK][CH];
__device__ __nv_bfloat16 g_kh[BATCH][NTOK][CH];
__device__ __nv_bfloat16 g_kl[BATCH][NTOK][CH];
__device__ __nv_bfloat16 g_v [BATCH][CH][NTOK];
__device__ float g_O [BATCH][2][NTOK][CH];   // unnormalized partial O
__device__ float g_ms[BATCH][2][NTOK];       // row max (of 1.3*s)
__device__ float g_ls[BATCH][2][NTOK];       // row sum

// ---------------- smem for fused attention ----------------
struct SmemT {
    __nv_bfloat16 kh[2][64][136];   // [stage][m][c]  64 tok x 128 ch (+8 pad)
    __nv_bfloat16 kl[2][64][136];
    __nv_bfloat16 v [2][128][72];   // [stage][c][m]  128 ch x 64 tok (+8 pad)
};

// ---------------- helpers ----------------
__device__ __forceinline__ void ldsm4(uint32_t r[4], const void* p) {
    uint32_t a = (uint32_t)__cvta_generic_to_shared(p);
    asm volatile("ldmatrix.sync.aligned.m8n8.x4.shared.b16 {%0,%1,%2,%3}, [%4];\n"
                 : "=r"(r[0]), "=r"(r[1]), "=r"(r[2]), "=r"(r[3]) : "r"(a));
}
__device__ __forceinline__ void mma_bf16(float c[4], const uint32_t a[4], uint32_t b0, uint32_t b1) {
    asm volatile("mma.sync.aligned.m16n8k16.row.col.f32.bf16.bf16.f32 "
                 "{%0,%1,%2,%3},{%4,%5,%6,%7},{%8,%9},{%0,%1,%2,%3};\n"
                 : "+f"(c[0]), "+f"(c[1]), "+f"(c[2]), "+f"(c[3])
                 : "r"(a[0]), "r"(a[1]), "r"(a[2]), "r"(a[3]), "r"(b0), "r"(b1));
}
__device__ __forceinline__ void cpa16(void* dst, const void* src) {
    uint32_t d = (uint32_t)__cvta_generic_to_shared(dst);
    asm volatile("cp.async.cg.shared.global [%0], [%1], 16;\n" :: "r"(d), "l"(src));
}
#define CP_COMMIT() asm volatile("cp.async.commit_group;\n")
#define CP_WAIT(n)  asm volatile("cp.async.wait_group %0;\n" :: "n"(n))

// 3072 x 16B chunks: kh 1024 (64 rows x 16 chunks), kl 1024, v 1024 (128 rows x 8)
__device__ __forceinline__ void issue_tile(SmemT* sm, int b, int half, int tt, int st, int tid) {
    const int m0 = half * HALF_M + tt * KT;
    #pragma unroll
    for (int i = tid; i < 3072; i += 256) {
        if (i < 1024) {
            int r = i >> 4, ch = i & 15;
            cpa16(&sm->kh[st][r][ch * 8], &g_kh[b][m0 + r][ch * 8]);
        } else if (i < 2048) {
            int j = i - 1024, r = j >> 4, ch = j & 15;
            cpa16(&sm->kl[st][r][ch * 8], &g_kl[b][m0 + r][ch * 8]);
        } else {
            int j = i - 2048, r = j >> 3, ch = j & 7;
            cpa16(&sm->v[st][r][ch * 8], &g_v[b][r][m0 + ch * 8]);
        }
    }
}

// ---------------- K1: QKV projection (fp32) + bf16 hi/lo split ----------------
__global__ __launch_bounds__(256) void k1_proj(
    const float* __restrict__ x,
    const float* __restrict__ Wq, const float* __restrict__ bq,
    const float* __restrict__ Wk, const float* __restrict__ bk,
    const float* __restrict__ Wv, const float* __restrict__ bv)
{
    const int n0  = blockIdx.x * 128;
    const int mat = blockIdx.y;
    const int b   = blockIdx.z;
    const float* W    = (mat == 0) ? Wq : (mat == 1) ? Wk : Wv;
    const float* bias = (mat == 0) ? bq : (mat == 1) ? bk : bv;

    __shared__ float sW[32][132];
    __shared__ float sX[32][128];

    const int t  = threadIdx.x;
    const int n4 = (t & 31) * 4;
    const int ob = (t >> 5) * 16;

    float acc[16][4];
    #pragma unroll
    for (int i = 0; i < 16; i++)
        #pragma unroll
        for (int j = 0; j < 4; j++) acc[i][j] = 0.f;

    const float* xb = x + (size_t)b * CH * NTOK;

    for (int c0 = 0; c0 < 128; c0 += 32) {
        __syncthreads();
        for (int i = t; i < 128 * 8; i += 256) {
            int o = i >> 3, u = i & 7;
            float4 w4 = *(const float4*)(W + o * 128 + c0 + u * 4);
            sW[u * 4 + 0][o] = w4.x; sW[u * 4 + 1][o] = w4.y;
            sW[u * 4 + 2][o] = w4.z; sW[u * 4 + 3][o] = w4.w;
        }
        for (int i = t; i < 32 * 32; i += 256) {
            int r = i >> 5, u = i & 31;
            *(float4*)&sX[r][u * 4] = *(const float4*)(xb + (size_t)(c0 + r) * NTOK + n0 + u * 4);
        }
        __syncthreads();
        #pragma unroll
        for (int c = 0; c < 32; c++) {
            float4 xv = *(float4*)&sX[c][n4];
            #pragma unroll
            for (int iq = 0; iq < 4; iq++) {
                float4 wv = *(float4*)&sW[c][ob + iq * 4];
                float wr[4] = {wv.x, wv.y, wv.z, wv.w};
                #pragma unroll
                for (int jj = 0; jj < 4; jj++) {
                    acc[iq * 4 + jj][0] += wr[jj] * xv.x;
                    acc[iq * 4 + jj][1] += wr[jj] * xv.y;
                    acc[iq * 4 + jj][2] += wr[jj] * xv.z;
                    acc[iq * 4 + jj][3] += wr[jj] * xv.w;
                }
            }
        }
    }

    float bi[16];
    #pragma unroll
    for (int i = 0; i < 16; i++) bi[i] = bias[ob + i];

    if (mat == 2) {
        #pragma unroll
        for (int i = 0; i < 16; i++) {
            __align__(8) __nv_bfloat16 h[4];
            #pragma unroll
            for (int j = 0; j < 4; j++) h[j] = __float2bfloat16(acc[i][j] + bi[i]);
            *(uint2*)&g_v[b][ob + i][n0 + n4] = *(uint2*)h;
        }
    } else {
        __nv_bfloat16 (*dh)[NTOK][CH] = (mat == 0) ? g_qh : g_kh;
        __nv_bfloat16 (*dl)[NTOK][CH] = (mat == 0) ? g_ql : g_kl;
        #pragma unroll
        for (int j = 0; j < 4; j++) {
            __align__(16) __nv_bfloat16 hh[16];
            __align__(16) __nv_bfloat16 ll[16];
            #pragma unroll
            for (int i = 0; i < 16; i++) {
                float v = acc[i][j] + bi[i];
                __nv_bfloat16 h = __float2bfloat16(v);
                hh[i] = h;
                ll[i] = __float2bfloat16(v - __bfloat162float(h));
            }
            int n = n0 + n4 + j;
            *(uint4*)&dh[b][n][ob + 0] = *(uint4*)&hh[0];
            *(uint4*)&dh[b][n][ob + 8] = *(uint4*)&hh[8];
            *(uint4*)&dl[b][n][ob + 0] = *(uint4*)&ll[0];
            *(uint4*)&dl[b][n][ob + 8] = *(uint4*)&ll[8];
        }
    }
}

// ---------------- K2: fused flash attention (split-K=2 over kv) ----------------
__global__ __launch_bounds__(256, 1) void k2_attn() {
    extern __shared__ char smem_raw[];
    SmemT* sm = (SmemT*)smem_raw;

    const int n0   = blockIdx.x * 128;
    const int half = blockIdx.y;
    const int b    = blockIdx.z;
    const int t    = threadIdx.x, wid = t >> 5, ln = t & 31;

    // ---- load Q fragments (hi/lo) into registers, staged through smem ----
    uint32_t qh[8][4], ql[8][4];
    for (int round = 0; round < 2; round++) {
        for (int i = t; i < 1024; i += 256) {
            int r = i >> 4, ch = i & 15;
            *(uint4*)&sm->kh[0][r][ch * 8] = *(const uint4*)&g_qh[b][n0 + round * 64 + r][ch * 8];
            *(uint4*)&sm->kl[0][r][ch * 8] = *(const uint4*)&g_ql[b][n0 + round * 64 + r][ch * 8];
        }
        __syncthreads();
        if ((wid >> 2) == round) {
            int wl = (wid & 3) * 16;
            #pragma unroll
            for (int ks = 0; ks < 8; ks++) {
                ldsm4(qh[ks], &sm->kh[0][wl + (ln & 15)][ks * 16 + (ln >> 4) * 8]);
                ldsm4(ql[ks], &sm->kl[0][wl + (ln & 15)][ks * 16 + (ln >> 4) * 8]);
            }
        }
        __syncthreads();
    }

    float o[16][4];
    #pragma unroll
    for (int i = 0; i < 16; i++)
        #pragma unroll
        for (int j = 0; j < 4; j++) o[i][j] = 0.f;
    float rm0 = -1e30f, rm1 = -1e30f, rl0 = 0.f, rl1 = 0.f;

    issue_tile(sm, b, half, 0, 0, t);
    CP_COMMIT();

    for (int tt = 0; tt < NTILES; tt++) {
        const int st = tt & 1;
        if (tt + 1 < NTILES) {
            issue_tile(sm, b, half, tt + 1, (tt + 1) & 1, t);
            CP_COMMIT();
            CP_WAIT(1);
        } else {
            CP_WAIT(0);
        }
        __syncthreads();

        // ---- S = 1.3*(qh·kh + qh·kl + ql·kh) : 16 rows x 64 m per warp ----
        float s[8][4];
        #pragma unroll
        for (int i = 0; i < 8; i++)
            #pragma unroll
            for (int j = 0; j < 4; j++) s[i][j] = 0.f;

        #pragma unroll
        for (int ks = 0; ks < 8; ks++) {
            const int kk = ks * 16;
            uint32_t bh[4][4], bl[4][4];
            #pragma unroll
            for (int g = 0; g < 4; g++) {
                int rr = g * 16 + (ln & 7) + ((ln >> 4) << 3);
                int cc = kk + (((ln >> 3) & 1) << 3);
                ldsm4(bh[g], &sm->kh[st][rr][cc]);
                ldsm4(bl[g], &sm->kl[st][rr][cc]);
            }
            #pragma unroll
            for (int g = 0; g < 4; g++)
                #pragma unroll
                for (int j = 0; j < 2; j++) {
                    const int ni = g * 2 + j;
                    mma_bf16(s[ni], qh[ks], bh[g][j * 2], bh[g][j * 2 + 1]);
                    mma_bf16(s[ni], qh[ks], bl[g][j * 2], bl[g][j * 2 + 1]);
                    mma_bf16(s[ni], ql[ks], bh[g][j * 2], bh[g][j * 2 + 1]);
                }
        }

        // ---- online softmax (rows fully warp-owned; quad-lane reductions) ----
        #pragma unroll
        for (int i = 0; i < 8; i++)
            #pragma unroll
            for (int j = 0; j < 4; j++) s[i][j] *= 1.3f;

        float tm0 = -1e30f, tm1 = -1e30f;
        #pragma unroll
        for (int i = 0; i < 8; i++) {
            tm0 = fmaxf(tm0, fmaxf(s[i][0], s[i][1]));
            tm1 = fmaxf(tm1, fmaxf(s[i][2], s[i][3]));
        }
        tm0 = fmaxf(tm0, __shfl_xor_sync(0xffffffffu, tm0, 1));
        tm0 = fmaxf(tm0, __shfl_xor_sync(0xffffffffu, tm0, 2));
        tm1 = fmaxf(tm1, __shfl_xor_sync(0xffffffffu, tm1, 1));
        tm1 = fmaxf(tm1, __shfl_xor_sync(0xffffffffu, tm1, 2));

        const float mn0 = fmaxf(rm0, tm0), mn1 = fmaxf(rm1, tm1);
        const float sc0 = __expf(rm0 - mn0), sc1 = __expf(rm1 - mn1);
        rm0 = mn0; rm1 = mn1;

        float ts0 = 0.f, ts1 = 0.f;
        #pragma unroll
        for (int i = 0; i < 8; i++) {
            s[i][0] = __expf(s[i][0] - mn0);
            s[i][1] = __expf(s[i][1] - mn0);
            s[i][2] = __expf(s[i][2] - mn1);
            s[i][3] = __expf(s[i][3] - mn1);
            ts0 += s[i][0] + s[i][1];
            ts1 += s[i][2] + s[i][3];
        }
        ts0 += __shfl_xor_sync(0xffffffffu, ts0, 1);
        ts0 += __shfl_xor_sync(0xffffffffu, ts0, 2);
        ts1 += __shfl_xor_sync(0xffffffffu, ts1, 1);
        ts1 += __shfl_xor_sync(0xffffffffu, ts1, 2);
        rl0 = rl0 * sc0 + ts0;
        rl1 = rl1 * sc1 + ts1;

        #pragma unroll
        for (int i = 0; i < 16; i++) {
            o[i][0] *= sc0; o[i][1] *= sc0;
            o[i][2] *= sc1; o[i][3] *= sc1;
        }

        // ---- repack P (C-frag -> A-frag) ----
        uint32_t pf[4][4];
        #pragma unroll
        for (int kp = 0; kp < 4; kp++) {
            __nv_bfloat162 h;
            h = __floats2bfloat162_rn(s[2*kp][0],   s[2*kp][1]);   pf[kp][0] = *(uint32_t*)&h;
            h = __floats2bfloat162_rn(s[2*kp][2],   s[2*kp][3]);   pf[kp][1] = *(uint32_t*)&h;
            h = __floats2bfloat162_rn(s[2*kp+1][0], s[2*kp+1][1]); pf[kp][2] = *(uint32_t*)&h;
            h = __floats2bfloat162_rn(s[2*kp+1][2], s[2*kp+1][3]); pf[kp][3] = *(uint32_t*)&h;
        }

        // ---- O += P · V^T ----
        #pragma unroll
        for (int kp = 0; kp < 4; kp++) {
            #pragma unroll
            for (int cg = 0; cg < 8; cg++) {
                uint32_t vb[4];
                ldsm4(vb, &sm->v[st][cg * 16 + (ln & 7) + ((ln >> 4) << 3)]
                                    [kp * 16 + (((ln >> 3) & 1) << 3)]);
                mma_bf16(o[cg * 2],     pf[kp], vb[0], vb[1]);
                mma_bf16(o[cg * 2 + 1], pf[kp], vb[2], vb[3]);
            }
        }
        __syncthreads();
    }

    // ---- epilogue: unnormalized O + row stats ----
    const int gr = ln >> 2;
    const int r0 = n0 + wid * 16 + gr, r1 = r0 + 8;
    float* O0 = &g_O[b][half][0][0];
    #pragma unroll
    for (int ni = 0; ni < 16; ni++) {
        int c = ni * 8 + (ln & 3) * 2;
        *(float2*)(O0 + (size_t)r0 * CH + c) = make_float2(o[ni][0], o[ni][1]);
        *(float2*)(O0 + (size_t)r1 * CH + c) = make_float2(o[ni][2], o[ni][3]);
    }
    if ((ln & 3) == 0) {
        g_ms[b][half][r0] = rm0; g_ls[b][half][r0] = rl0;
        g_ms[b][half][r1] = rm1; g_ls[b][half][r1] = rl1;
    }
}

// ---------------- K5: LSE combine, transpose, residual ----------------
__global__ __launch_bounds__(256) void k5_reduce(
    const float* __restrict__ x, const float* __restrict__ gamma,
    float* __restrict__ out)
{
    const int n0 = blockIdx.x * 32;
    const int b  = blockIdx.y;
    const int t  = threadIdx.x;
    const float g = *gamma;

    __shared__ float s[128][33];
    __shared__ float f0[32], f1[32];

    if (t < 32) {
        int n = n0 + t;
        float m1 = g_ms[b][0][n], l1 = g_ls[b][0][n];
        float m2 = g_ms[b][1][n], l2 = g_ls[b][1][n];
        float M  = fmaxf(m1, m2);
        float w1 = __expf(m1 - M), w2 = __expf(m2 - M);
        float inv = 1.0f / (w1 * l1 + w2 * l2);
        f0[t] = w1 * inv; f1[t] = w2 * inv;
    }
    __syncthreads();

    for (int i = t; i < 32 * 128; i += 256) {
        int nl = i >> 7, c = i & 127;
        s[c][nl] = f0[nl] * g_O[b][0][n0 + nl][c] + f1[nl] * g_O[b][1][n0 + nl][c];
    }
    __syncthreads();
    const size_t base = (size_t)b * CH * NTOK;
    for (int i = t; i < 128 * 32; i += 256) {
        int c = i >> 5, nl = i & 31;
        size_t idx = base + (size_t)c * NTOK + n0 + nl;
        out[idx] = x[idx] + g * s[c][nl];
    }
}

extern "C" void kernel_launch(void* const* d_in, const int* in_sizes, int n_in,
                              void* d_out, int out_size) {
    const float* x  = (const float*)d_in[0];
    const float* Wq = (const float*)d_in[1];
    const float* bq = (const float*)d_in[2];
    const float* Wk = (const float*)d_in[3];
    const float* bk = (const float*)d_in[4];
    const float* Wv = (const float*)d_in[5];
    const float* bv = (const float*)d_in[6];
    const float* gm = (const float*)d_in[7];
    float* out = (float*)d_out;

    cudaFuncSetAttribute(k2_attn, cudaFuncAttributeMaxDynamicSharedMemorySize,
                         (int)sizeof(SmemT));

    k1_proj  <<<dim3(NTOK / 128, 3, BATCH), 256>>>(x, Wq, bq, Wk, bk, Wv, bv);
    k2_attn  <<<dim3(NTOK / 128, 2, BATCH), 256, sizeof(SmemT)>>>();
    k5_reduce<<<dim3(NTOK / 32, BATCH),     256>>>(x, gm, out);
}

// round 13
// speedup vs baseline: 1.4507x; 1.0271x over previous
#include <cuda_runtime.h>
#include <cuda_bf16.h>
#include <cstdint>

#define BATCH 2
#define CH    128
#define NTOK  4096
#define KT    64
#define HALF_M 2048
#define NTILES 32

// ---------------- scratch (device .bss — no allocation) ----------------
__device__ __nv_bfloat16 g_qh[BATCH][NTOK][CH];   // q pre-scaled by 1.3
__device__ __nv_bfloat16 g_ql[BATCH][NTOK][CH];
__device__ __nv_bfloat16 g_kh[BATCH][NTOK][CH];
__device__ __nv_bfloat16 g_kl[BATCH][NTOK][CH];
__device__ __nv_bfloat16 g_v [BATCH][CH][NTOK];
__device__ float g_O [BATCH][2][NTOK][CH];
__device__ float g_ms[BATCH][2][NTOK];
__device__ float g_ls[BATCH][2][NTOK];

// ---------------- smem for fused attention ----------------
struct SmemT {
    __nv_bfloat16 kh[2][64][136];
    __nv_bfloat16 kl[2][64][136];
    __nv_bfloat16 v [2][128][72];
};

// ---------------- helpers ----------------
__device__ __forceinline__ void ldsm4(uint32_t r[4], const void* p) {
    uint32_t a = (uint32_t)__cvta_generic_to_shared(p);
    asm volatile("ldmatrix.sync.aligned.m8n8.x4.shared.b16 {%0,%1,%2,%3}, [%4];\n"
                 : "=r"(r[0]), "=r"(r[1]), "=r"(r[2]), "=r"(r[3]) : "r"(a));
}
__device__ __forceinline__ void mma_bf16(float c[4], const uint32_t a[4], uint32_t b0, uint32_t b1) {
    asm volatile("mma.sync.aligned.m16n8k16.row.col.f32.bf16.bf16.f32 "
                 "{%0,%1,%2,%3},{%4,%5,%6,%7},{%8,%9},{%0,%1,%2,%3};\n"
                 : "+f"(c[0]), "+f"(c[1]), "+f"(c[2]), "+f"(c[3])
                 : "r"(a[0]), "r"(a[1]), "r"(a[2]), "r"(a[3]), "r"(b0), "r"(b1));
}
__device__ __forceinline__ void cpa16(void* dst, const void* src) {
    uint32_t d = (uint32_t)__cvta_generic_to_shared(dst);
    asm volatile("cp.async.cg.shared.global [%0], [%1], 16;\n" :: "r"(d), "l"(src));
}
#define CP_COMMIT() asm volatile("cp.async.commit_group;\n")
#define CP_WAIT(n)  asm volatile("cp.async.wait_group %0;\n" :: "n"(n))

__device__ __forceinline__ void issue_tile(SmemT* sm, int b, int half, int tt, int st, int tid) {
    const int m0 = half * HALF_M + tt * KT;
    #pragma unroll
    for (int i = tid; i < 3072; i += 256) {
        if (i < 1024) {
            int r = i >> 4, ch = i & 15;
            cpa16(&sm->kh[st][r][ch * 8], &g_kh[b][m0 + r][ch * 8]);
        } else if (i < 2048) {
            int j = i - 1024, r = j >> 4, ch = j & 15;
            cpa16(&sm->kl[st][r][ch * 8], &g_kl[b][m0 + r][ch * 8]);
        } else {
            int j = i - 2048, r = j >> 3, ch = j & 7;
            cpa16(&sm->v[st][r][ch * 8], &g_v[b][r][m0 + ch * 8]);
        }
    }
}

// ---------------- K1: QKV projection (fp32), n-tile 64, 384 CTAs ----------------
__global__ __launch_bounds__(256) void k1_proj(
    const float* __restrict__ x,
    const float* __restrict__ Wq, const float* __restrict__ bq,
    const float* __restrict__ Wk, const float* __restrict__ bk,
    const float* __restrict__ Wv, const float* __restrict__ bv)
{
    const int n0  = blockIdx.x * 64;
    const int mat = blockIdx.y;
    const int b   = blockIdx.z;
    const float* W    = (mat == 0) ? Wq : (mat == 1) ? Wk : Wv;
    const float* bias = (mat == 0) ? bq : (mat == 1) ? bk : bv;

    __shared__ float sW[32][132];   // [c-local][o], transposed, padded
    __shared__ float sX[32][64];    // [c-local][n-local]

    const int t  = threadIdx.x;
    const int n4 = (t & 15) * 4;    // 16 groups x 4 n = 64 n
    const int ob = (t >> 4) * 8;    // 16 groups x 8 o = 128 o

    float acc[8][4];
    #pragma unroll
    for (int i = 0; i < 8; i++)
        #pragma unroll
        for (int j = 0; j < 4; j++) acc[i][j] = 0.f;

    const float* xb = x + (size_t)b * CH * NTOK;

    for (int c0 = 0; c0 < 128; c0 += 32) {
        __syncthreads();
        for (int i = t; i < 128 * 8; i += 256) {
            int o = i >> 3, u = i & 7;
            float4 w4 = *(const float4*)(W + o * 128 + c0 + u * 4);
            sW[u * 4 + 0][o] = w4.x; sW[u * 4 + 1][o] = w4.y;
            sW[u * 4 + 2][o] = w4.z; sW[u * 4 + 3][o] = w4.w;
        }
        for (int i = t; i < 512; i += 256) {
            int r = i >> 4, u = i & 15;
            *(float4*)&sX[r][u * 4] = *(const float4*)(xb + (size_t)(c0 + r) * NTOK + n0 + u * 4);
        }
        __syncthreads();
        #pragma unroll
        for (int c = 0; c < 32; c++) {
            float4 xv = *(float4*)&sX[c][n4];
            #pragma unroll
            for (int iq = 0; iq < 2; iq++) {
                float4 wv = *(float4*)&sW[c][ob + iq * 4];
                float wr[4] = {wv.x, wv.y, wv.z, wv.w};
                #pragma unroll
                for (int jj = 0; jj < 4; jj++) {
                    acc[iq * 4 + jj][0] += wr[jj] * xv.x;
                    acc[iq * 4 + jj][1] += wr[jj] * xv.y;
                    acc[iq * 4 + jj][2] += wr[jj] * xv.z;
                    acc[iq * 4 + jj][3] += wr[jj] * xv.w;
                }
            }
        }
    }

    float bi[8];
    #pragma unroll
    for (int i = 0; i < 8; i++) bi[i] = bias[ob + i];
    const float scale = (mat == 0) ? 1.3f : 1.0f;   // fold logit scale into q

    if (mat == 2) {
        #pragma unroll
        for (int i = 0; i < 8; i++) {
            __align__(8) __nv_bfloat16 h[4];
            #pragma unroll
            for (int j = 0; j < 4; j++) h[j] = __float2bfloat16(acc[i][j] + bi[i]);
            *(uint2*)&g_v[b][ob + i][n0 + n4] = *(uint2*)h;
        }
    } else {
        __nv_bfloat16 (*dh)[NTOK][CH] = (mat == 0) ? g_qh : g_kh;
        __nv_bfloat16 (*dl)[NTOK][CH] = (mat == 0) ? g_ql : g_kl;
        #pragma unroll
        for (int j = 0; j < 4; j++) {
            __align__(16) __nv_bfloat16 hh[8];
            __align__(16) __nv_bfloat16 ll[8];
            #pragma unroll
            for (int i = 0; i < 8; i++) {
                float v = (acc[i][j] + bi[i]) * scale;
                __nv_bfloat16 h = __float2bfloat16(v);
                hh[i] = h;
                ll[i] = __float2bfloat16(v - __bfloat162float(h));
            }
            int n = n0 + n4 + j;
            *(uint4*)&dh[b][n][ob] = *(uint4*)&hh[0];
            *(uint4*)&dl[b][n][ob] = *(uint4*)&ll[0];
        }
    }
}

// ---------------- K2: fused flash attention (split-K=2 over kv) ----------------
__global__ __launch_bounds__(256, 1) void k2_attn() {
    extern __shared__ char smem_raw[];
    SmemT* sm = (SmemT*)smem_raw;

    const int n0   = blockIdx.x * 128;
    const int half = blockIdx.y;
    const int b    = blockIdx.z;
    const int t    = threadIdx.x, wid = t >> 5, ln = t & 31;

    // ---- load Q fragments (hi/lo) into registers, staged through smem ----
    uint32_t qh[8][4], ql[8][4];
    for (int round = 0; round < 2; round++) {
        for (int i = t; i < 1024; i += 256) {
            int r = i >> 4, ch = i & 15;
            *(uint4*)&sm->kh[0][r][ch * 8] = *(const uint4*)&g_qh[b][n0 + round * 64 + r][ch * 8];
            *(uint4*)&sm->kl[0][r][ch * 8] = *(const uint4*)&g_ql[b][n0 + round * 64 + r][ch * 8];
        }
        __syncthreads();
        if ((wid >> 2) == round) {
            int wl = (wid & 3) * 16;
            #pragma unroll
            for (int ks = 0; ks < 8; ks++) {
                ldsm4(qh[ks], &sm->kh[0][wl + (ln & 15)][ks * 16 + (ln >> 4) * 8]);
                ldsm4(ql[ks], &sm->kl[0][wl + (ln & 15)][ks * 16 + (ln >> 4) * 8]);
            }
        }
        __syncthreads();
    }

    float o[16][4];
    #pragma unroll
    for (int i = 0; i < 16; i++)
        #pragma unroll
        for (int j = 0; j < 4; j++) o[i][j] = 0.f;
    float rm0 = -1e30f, rm1 = -1e30f, rl0 = 0.f, rl1 = 0.f;

    issue_tile(sm, b, half, 0, 0, t);
    CP_COMMIT();

    for (int tt = 0; tt < NTILES; tt++) {
        const int st = tt & 1;
        if (tt + 1 < NTILES) {
            issue_tile(sm, b, half, tt + 1, (tt + 1) & 1, t);
            CP_COMMIT();
            CP_WAIT(1);
        } else {
            CP_WAIT(0);
        }
        __syncthreads();

        // ---- S = qh·kh + qh·kl + ql·kh  (q pre-scaled by 1.3) ----
        float s[8][4];
        #pragma unroll
        for (int i = 0; i < 8; i++)
            #pragma unroll
            for (int j = 0; j < 4; j++) s[i][j] = 0.f;

        #pragma unroll
        for (int ks = 0; ks < 8; ks++) {
            const int kk = ks * 16;
            uint32_t bh[4][4], bl[4][4];
            #pragma unroll
            for (int g = 0; g < 4; g++) {
                int rr = g * 16 + (ln & 7) + ((ln >> 4) << 3);
                int cc = kk + (((ln >> 3) & 1) << 3);
                ldsm4(bh[g], &sm->kh[st][rr][cc]);
                ldsm4(bl[g], &sm->kl[st][rr][cc]);
            }
            #pragma unroll
            for (int g = 0; g < 4; g++)
                #pragma unroll
                for (int j = 0; j < 2; j++) {
                    const int ni = g * 2 + j;
                    mma_bf16(s[ni], qh[ks], bh[g][j * 2], bh[g][j * 2 + 1]);
                    mma_bf16(s[ni], qh[ks], bl[g][j * 2], bl[g][j * 2 + 1]);
                    mma_bf16(s[ni], ql[ks], bh[g][j * 2], bh[g][j * 2 + 1]);
                }
        }

        // ---- online softmax ----
        float tm0 = -1e30f, tm1 = -1e30f;
        #pragma unroll
        for (int i = 0; i < 8; i++) {
            tm0 = fmaxf(tm0, fmaxf(s[i][0], s[i][1]));
            tm1 = fmaxf(tm1, fmaxf(s[i][2], s[i][3]));
        }
        tm0 = fmaxf(tm0, __shfl_xor_sync(0xffffffffu, tm0, 1));
        tm0 = fmaxf(tm0, __shfl_xor_sync(0xffffffffu, tm0, 2));
        tm1 = fmaxf(tm1, __shfl_xor_sync(0xffffffffu, tm1, 1));
        tm1 = fmaxf(tm1, __shfl_xor_sync(0xffffffffu, tm1, 2));

        const float mn0 = fmaxf(rm0, tm0), mn1 = fmaxf(rm1, tm1);
        const float sc0 = __expf(rm0 - mn0), sc1 = __expf(rm1 - mn1);
        rm0 = mn0; rm1 = mn1;

        float ts0 = 0.f, ts1 = 0.f;
        #pragma unroll
        for (int i = 0; i < 8; i++) {
            s[i][0] = __expf(s[i][0] - mn0);
            s[i][1] = __expf(s[i][1] - mn0);
            s[i][2] = __expf(s[i][2] - mn1);
            s[i][3] = __expf(s[i][3] - mn1);
            ts0 += s[i][0] + s[i][1];
            ts1 += s[i][2] + s[i][3];
        }
        ts0 += __shfl_xor_sync(0xffffffffu, ts0, 1);
        ts0 += __shfl_xor_sync(0xffffffffu, ts0, 2);
        ts1 += __shfl_xor_sync(0xffffffffu, ts1, 1);
        ts1 += __shfl_xor_sync(0xffffffffu, ts1, 2);
        rl0 = rl0 * sc0 + ts0;
        rl1 = rl1 * sc1 + ts1;

        #pragma unroll
        for (int i = 0; i < 16; i++) {
            o[i][0] *= sc0; o[i][1] *= sc0;
            o[i][2] *= sc1; o[i][3] *= sc1;
        }

        // ---- repack P (C-frag -> A-frag) ----
        uint32_t pf[4][4];
        #pragma unroll
        for (int kp = 0; kp < 4; kp++) {
            __nv_bfloat162 h;
            h = __floats2bfloat162_rn(s[2*kp][0],   s[2*kp][1]);   pf[kp][0] = *(uint32_t*)&h;
            h = __floats2bfloat162_rn(s[2*kp][2],   s[2*kp][3]);   pf[kp][1] = *(uint32_t*)&h;
            h = __floats2bfloat162_rn(s[2*kp+1][0], s[2*kp+1][1]); pf[kp][2] = *(uint32_t*)&h;
            h = __floats2bfloat162_rn(s[2*kp+1][2], s[2*kp+1][3]); pf[kp][3] = *(uint32_t*)&h;
        }

        // ---- O += P · V^T ----
        #pragma unroll
        for (int kp = 0; kp < 4; kp++) {
            #pragma unroll
            for (int cg = 0; cg < 8; cg++) {
                uint32_t vb[4];
                ldsm4(vb, &sm->v[st][cg * 16 + (ln & 7) + ((ln >> 4) << 3)]
                                    [kp * 16 + (((ln >> 3) & 1) << 3)]);
                mma_bf16(o[cg * 2],     pf[kp], vb[0], vb[1]);
                mma_bf16(o[cg * 2 + 1], pf[kp], vb[2], vb[3]);
            }
        }
        __syncthreads();
    }

    // ---- epilogue: unnormalized O + row stats ----
    const int gr = ln >> 2;
    const int r0 = n0 + wid * 16 + gr, r1 = r0 + 8;
    float* O0 = &g_O[b][half][0][0];
    #pragma unroll
    for (int ni = 0; ni < 16; ni++) {
        int c = ni * 8 + (ln & 3) * 2;
        *(float2*)(O0 + (size_t)r0 * CH + c) = make_float2(o[ni][0], o[ni][1]);
        *(float2*)(O0 + (size_t)r1 * CH + c) = make_float2(o[ni][2], o[ni][3]);
    }
    if ((ln & 3) == 0) {
        g_ms[b][half][r0] = rm0; g_ls[b][half][r0] = rl0;
        g_ms[b][half][r1] = rm1; g_ls[b][half][r1] = rl1;
    }
}

// ---------------- K5: LSE combine, transpose, residual ----------------
__global__ __launch_bounds__(256) void k5_reduce(
    const float* __restrict__ x, const float* __restrict__ gamma,
    float* __restrict__ out)
{
    const int n0 = blockIdx.x * 32;
    const int b  = blockIdx.y;
    const int t  = threadIdx.x;
    const float g = *gamma;

    __shared__ float s[128][33];
    __shared__ float f0[32], f1[32];

    if (t < 32) {
        int n = n0 + t;
        float m1 = g_ms[b][0][n], l1 = g_ls[b][0][n];
        float m2 = g_ms[b][1][n], l2 = g_ls[b][1][n];
        float M  = fmaxf(m1, m2);
        float w1 = __expf(m1 - M), w2 = __expf(m2 - M);
        float inv = 1.0f / (w1 * l1 + w2 * l2);
        f0[t] = w1 * inv; f1[t] = w2 * inv;
    }
    __syncthreads();

    for (int i = t; i < 32 * 128; i += 256) {
        int nl = i >> 7, c = i & 127;
        s[c][nl] = f0[nl] * g_O[b][0][n0 + nl][c] + f1[nl] * g_O[b][1][n0 + nl][c];
    }
    __syncthreads();
    const size_t base = (size_t)b * CH * NTOK;
    for (int i = t; i < 128 * 32; i += 256) {
        int c = i >> 5, nl = i & 31;
        size_t idx = base + (size_t)c * NTOK + n0 + nl;
        out[idx] = x[idx] + g * s[c][nl];
    }
}

extern "C" void kernel_launch(void* const* d_in, const int* in_sizes, int n_in,
                              void* d_out, int out_size) {
    const float* x  = (const float*)d_in[0];
    const float* Wq = (const float*)d_in[1];
    const float* bq = (const float*)d_in[2];
    const float* Wk = (const float*)d_in[3];
    const float* bk = (const float*)d_in[4];
    const float* Wv = (const float*)d_in[5];
    const float* bv = (const float*)d_in[6];
    const float* gm = (const float*)d_in[7];
    float* out = (float*)d_out;

    cudaFuncSetAttribute(k2_attn, cudaFuncAttributeMaxDynamicSharedMemorySize,
                         (int)sizeof(SmemT));

    k1_proj  <<<dim3(NTOK / 64, 3, BATCH), 256>>>(x, Wq, bq, Wk, bk, Wv, bv);
    k2_attn  <<<dim3(NTOK / 128, 2, BATCH), 256, sizeof(SmemT)>>>();
    k5_reduce<<<dim3(NTOK / 32, BATCH),     256>>>(x, gm, out);
}

// round 14
// speedup vs baseline: 1.4552x; 1.0031x over previous
#include <cuda_runtime.h>
#include <cuda_bf16.h>
#include <cstdint>

#define BATCH 2
#define CH    128
#define NTOK  4096
#define KT    64
#define HALF_M 2048
#define NTILES 32

// ---------------- scratch (device .bss — no allocation) ----------------
__device__ __nv_bfloat16 g_qh[BATCH][NTOK][CH];   // q pre-scaled by 1.3
__device__ __nv_bfloat16 g_ql[BATCH][NTOK][CH];
__device__ __nv_bfloat16 g_kh[BATCH][NTOK][CH];
__device__ __nv_bfloat16 g_kl[BATCH][NTOK][CH];
__device__ __nv_bfloat16 g_v [BATCH][CH][NTOK];
__device__ float g_O [BATCH][2][NTOK][CH];
__device__ float g_ms[BATCH][2][NTOK];
__device__ float g_ls[BATCH][2][NTOK];

// ---------------- smem for fused attention ----------------
struct SmemT {
    __nv_bfloat16 kh[2][64][136];
    __nv_bfloat16 kl[2][64][136];
    __nv_bfloat16 v [2][128][72];
};

// ---------------- helpers ----------------
__device__ __forceinline__ void ldsm4(uint32_t r[4], const void* p) {
    uint32_t a = (uint32_t)__cvta_generic_to_shared(p);
    asm volatile("ldmatrix.sync.aligned.m8n8.x4.shared.b16 {%0,%1,%2,%3}, [%4];\n"
                 : "=r"(r[0]), "=r"(r[1]), "=r"(r[2]), "=r"(r[3]) : "r"(a));
}
__device__ __forceinline__ void mma_bf16(float c[4], const uint32_t a[4], uint32_t b0, uint32_t b1) {
    asm volatile("mma.sync.aligned.m16n8k16.row.col.f32.bf16.bf16.f32 "
                 "{%0,%1,%2,%3},{%4,%5,%6,%7},{%8,%9},{%0,%1,%2,%3};\n"
                 : "+f"(c[0]), "+f"(c[1]), "+f"(c[2]), "+f"(c[3])
                 : "r"(a[0]), "r"(a[1]), "r"(a[2]), "r"(a[3]), "r"(b0), "r"(b1));
}
__device__ __forceinline__ void cpa16(void* dst, const void* src) {
    uint32_t d = (uint32_t)__cvta_generic_to_shared(dst);
    asm volatile("cp.async.cg.shared.global [%0], [%1], 16;\n" :: "r"(d), "l"(src));
}
#define CP_COMMIT() asm volatile("cp.async.commit_group;\n")
#define CP_WAIT(n)  asm volatile("cp.async.wait_group %0;\n" :: "n"(n))

__device__ __forceinline__ void issue_tile(SmemT* sm, int b, int half, int tt, int st, int tid) {
    const int m0 = half * HALF_M + tt * KT;
    #pragma unroll
    for (int i = tid; i < 3072; i += 256) {
        if (i < 1024) {
            int r = i >> 4, ch = i & 15;
            cpa16(&sm->kh[st][r][ch * 8], &g_kh[b][m0 + r][ch * 8]);
        } else if (i < 2048) {
            int j = i - 1024, r = j >> 4, ch = j & 15;
            cpa16(&sm->kl[st][r][ch * 8], &g_kl[b][m0 + r][ch * 8]);
        } else {
            int j = i - 2048, r = j >> 3, ch = j & 7;
            cpa16(&sm->v[st][r][ch * 8], &g_v[b][r][m0 + ch * 8]);
        }
    }
}

// ---------------- K1: QKV projection (fp32), n-tile 64, 384 CTAs ----------------
__global__ __launch_bounds__(256) void k1_proj(
    const float* __restrict__ x,
    const float* __restrict__ Wq, const float* __restrict__ bq,
    const float* __restrict__ Wk, const float* __restrict__ bk,
    const float* __restrict__ Wv, const float* __restrict__ bv)
{
    const int n0  = blockIdx.x * 64;
    const int mat = blockIdx.y;
    const int b   = blockIdx.z;
    const float* W    = (mat == 0) ? Wq : (mat == 1) ? Wk : Wv;
    const float* bias = (mat == 0) ? bq : (mat == 1) ? bk : bv;

    __shared__ float sW[32][132];   // [c-local][o], transposed, padded
    __shared__ float sX[32][64];    // [c-local][n-local]

    const int t  = threadIdx.x;
    const int n4 = (t & 15) * 4;    // 16 groups x 4 n = 64 n
    const int ob = (t >> 4) * 8;    // 16 groups x 8 o = 128 o

    float acc[8][4];
    #pragma unroll
    for (int i = 0; i < 8; i++)
        #pragma unroll
        for (int j = 0; j < 4; j++) acc[i][j] = 0.f;

    const float* xb = x + (size_t)b * CH * NTOK;

    for (int c0 = 0; c0 < 128; c0 += 32) {
        __syncthreads();
        for (int i = t; i < 128 * 8; i += 256) {
            int o = i >> 3, u = i & 7;
            float4 w4 = *(const float4*)(W + o * 128 + c0 + u * 4);
            sW[u * 4 + 0][o] = w4.x; sW[u * 4 + 1][o] = w4.y;
            sW[u * 4 + 2][o] = w4.z; sW[u * 4 + 3][o] = w4.w;
        }
        for (int i = t; i < 512; i += 256) {
            int r = i >> 4, u = i & 15;
            *(float4*)&sX[r][u * 4] = *(const float4*)(xb + (size_t)(c0 + r) * NTOK + n0 + u * 4);
        }
        __syncthreads();
        #pragma unroll
        for (int c = 0; c < 32; c++) {
            float4 xv = *(float4*)&sX[c][n4];
            #pragma unroll
            for (int iq = 0; iq < 2; iq++) {
                float4 wv = *(float4*)&sW[c][ob + iq * 4];
                float wr[4] = {wv.x, wv.y, wv.z, wv.w};
                #pragma unroll
                for (int jj = 0; jj < 4; jj++) {
                    acc[iq * 4 + jj][0] += wr[jj] * xv.x;
                    acc[iq * 4 + jj][1] += wr[jj] * xv.y;
                    acc[iq * 4 + jj][2] += wr[jj] * xv.z;
                    acc[iq * 4 + jj][3] += wr[jj] * xv.w;
                }
            }
        }
    }

    float bi[8];
    #pragma unroll
    for (int i = 0; i < 8; i++) bi[i] = bias[ob + i];
    const float scale = (mat == 0) ? 1.3f : 1.0f;   // fold logit scale into q

    if (mat == 2) {
        #pragma unroll
        for (int i = 0; i < 8; i++) {
            __align__(8) __nv_bfloat16 h[4];
            #pragma unroll
            for (int j = 0; j < 4; j++) h[j] = __float2bfloat16(acc[i][j] + bi[i]);
            *(uint2*)&g_v[b][ob + i][n0 + n4] = *(uint2*)h;
        }
    } else {
        __nv_bfloat16 (*dh)[NTOK][CH] = (mat == 0) ? g_qh : g_kh;
        __nv_bfloat16 (*dl)[NTOK][CH] = (mat == 0) ? g_ql : g_kl;
        #pragma unroll
        for (int j = 0; j < 4; j++) {
            __align__(16) __nv_bfloat16 hh[8];
            __align__(16) __nv_bfloat16 ll[8];
            #pragma unroll
            for (int i = 0; i < 8; i++) {
                float v = (acc[i][j] + bi[i]) * scale;
                __nv_bfloat16 h = __float2bfloat16(v);
                hh[i] = h;
                ll[i] = __float2bfloat16(v - __bfloat162float(h));
            }
            int n = n0 + n4 + j;
            *(uint4*)&dh[b][n][ob] = *(uint4*)&hh[0];
            *(uint4*)&dl[b][n][ob] = *(uint4*)&ll[0];
        }
    }
}

// ---------------- K2: fused flash attention (split-K=2 over kv) ----------------
__global__ __launch_bounds__(256, 1) void k2_attn() {
    extern __shared__ char smem_raw[];
    SmemT* sm = (SmemT*)smem_raw;

    const int n0   = blockIdx.x * 128;
    const int half = blockIdx.y;
    const int b    = blockIdx.z;
    const int t    = threadIdx.x, wid = t >> 5, ln = t & 31;

    // ---- load Q fragments (hi/lo) into registers, staged through smem ----
    uint32_t qh[8][4], ql[8][4];
    for (int round = 0; round < 2; round++) {
        for (int i = t; i < 1024; i += 256) {
            int r = i >> 4, ch = i & 15;
            *(uint4*)&sm->kh[0][r][ch * 8] = *(const uint4*)&g_qh[b][n0 + round * 64 + r][ch * 8];
            *(uint4*)&sm->kl[0][r][ch * 8] = *(const uint4*)&g_ql[b][n0 + round * 64 + r][ch * 8];
        }
        __syncthreads();
        if ((wid >> 2) == round) {
            int wl = (wid & 3) * 16;
            #pragma unroll
            for (int ks = 0; ks < 8; ks++) {
                ldsm4(qh[ks], &sm->kh[0][wl + (ln & 15)][ks * 16 + (ln >> 4) * 8]);
                ldsm4(ql[ks], &sm->kl[0][wl + (ln & 15)][ks * 16 + (ln >> 4) * 8]);
            }
        }
        __syncthreads();
    }

    float o[16][4];
    #pragma unroll
    for (int i = 0; i < 16; i++)
        #pragma unroll
        for (int j = 0; j < 4; j++) o[i][j] = 0.f;
    float rm0 = -1e30f, rm1 = -1e30f, rl0 = 0.f, rl1 = 0.f;

    issue_tile(sm, b, half, 0, 0, t);
    CP_COMMIT();

    for (int tt = 0; tt < NTILES; tt++) {
        const int st = tt & 1;
        if (tt + 1 < NTILES) {
            issue_tile(sm, b, half, tt + 1, (tt + 1) & 1, t);
            CP_COMMIT();
            CP_WAIT(1);
        } else {
            CP_WAIT(0);
        }
        __syncthreads();

        // ---- S = qh·kh + qh·kl + ql·kh  (q pre-scaled by 1.3) ----
        float s[8][4];
        #pragma unroll
        for (int i = 0; i < 8; i++)
            #pragma unroll
            for (int j = 0; j < 4; j++) s[i][j] = 0.f;

        #pragma unroll
        for (int ks = 0; ks < 8; ks++) {
            const int kk = ks * 16;
            uint32_t bh[4][4], bl[4][4];
            #pragma unroll
            for (int g = 0; g < 4; g++) {
                int rr = g * 16 + (ln & 7) + ((ln >> 4) << 3);
                int cc = kk + (((ln >> 3) & 1) << 3);
                ldsm4(bh[g], &sm->kh[st][rr][cc]);
                ldsm4(bl[g], &sm->kl[st][rr][cc]);
            }
            #pragma unroll
            for (int g = 0; g < 4; g++)
                #pragma unroll
                for (int j = 0; j < 2; j++) {
                    const int ni = g * 2 + j;
                    mma_bf16(s[ni], qh[ks], bh[g][j * 2], bh[g][j * 2 + 1]);
                    mma_bf16(s[ni], qh[ks], bl[g][j * 2], bl[g][j * 2 + 1]);
                    mma_bf16(s[ni], ql[ks], bh[g][j * 2], bh[g][j * 2 + 1]);
                }
        }

        // ---- online softmax ----
        float tm0 = -1e30f, tm1 = -1e30f;
        #pragma unroll
        for (int i = 0; i < 8; i++) {
            tm0 = fmaxf(tm0, fmaxf(s[i][0], s[i][1]));
            tm1 = fmaxf(tm1, fmaxf(s[i][2], s[i][3]));
        }
        tm0 = fmaxf(tm0, __shfl_xor_sync(0xffffffffu, tm0, 1));
        tm0 = fmaxf(tm0, __shfl_xor_sync(0xffffffffu, tm0, 2));
        tm1 = fmaxf(tm1, __shfl_xor_sync(0xffffffffu, tm1, 1));
        tm1 = fmaxf(tm1, __shfl_xor_sync(0xffffffffu, tm1, 2));

        const float mn0 = fmaxf(rm0, tm0), mn1 = fmaxf(rm1, tm1);
        const float sc0 = __expf(rm0 - mn0), sc1 = __expf(rm1 - mn1);
        rm0 = mn0; rm1 = mn1;

        float ts0 = 0.f, ts1 = 0.f;
        #pragma unroll
        for (int i = 0; i < 8; i++) {
            s[i][0] = __expf(s[i][0] - mn0);
            s[i][1] = __expf(s[i][1] - mn0);
            s[i][2] = __expf(s[i][2] - mn1);
            s[i][3] = __expf(s[i][3] - mn1);
            ts0 += s[i][0] + s[i][1];
            ts1 += s[i][2] + s[i][3];
        }
        ts0 += __shfl_xor_sync(0xffffffffu, ts0, 1);
        ts0 += __shfl_xor_sync(0xffffffffu, ts0, 2);
        ts1 += __shfl_xor_sync(0xffffffffu, ts1, 1);
        ts1 += __shfl_xor_sync(0xffffffffu, ts1, 2);
        rl0 = rl0 * sc0 + ts0;
        rl1 = rl1 * sc1 + ts1;

        #pragma unroll
        for (int i = 0; i < 16; i++) {
            o[i][0] *= sc0; o[i][1] *= sc0;
            o[i][2] *= sc1; o[i][3] *= sc1;
        }

        // ---- repack P (C-frag -> A-frag) ----
        uint32_t pf[4][4];
        #pragma unroll
        for (int kp = 0; kp < 4; kp++) {
            __nv_bfloat162 h;
            h = __floats2bfloat162_rn(s[2*kp][0],   s[2*kp][1]);   pf[kp][0] = *(uint32_t*)&h;
            h = __floats2bfloat162_rn(s[2*kp][2],   s[2*kp][3]);   pf[kp][1] = *(uint32_t*)&h;
            h = __floats2bfloat162_rn(s[2*kp+1][0], s[2*kp+1][1]); pf[kp][2] = *(uint32_t*)&h;
            h = __floats2bfloat162_rn(s[2*kp+1][2], s[2*kp+1][3]); pf[kp][3] = *(uint32_t*)&h;
        }

        // ---- O += P · V^T ----
        #pragma unroll
        for (int kp = 0; kp < 4; kp++) {
            #pragma unroll
            for (int cg = 0; cg < 8; cg++) {
                uint32_t vb[4];
                ldsm4(vb, &sm->v[st][cg * 16 + (ln & 7) + ((ln >> 4) << 3)]
                                    [kp * 16 + (((ln >> 3) & 1) << 3)]);
                mma_bf16(o[cg * 2],     pf[kp], vb[0], vb[1]);
                mma_bf16(o[cg * 2 + 1], pf[kp], vb[2], vb[3]);
            }
        }
        __syncthreads();
    }

    // ---- epilogue: unnormalized O + row stats ----
    const int gr = ln >> 2;
    const int r0 = n0 + wid * 16 + gr, r1 = r0 + 8;
    float* O0 = &g_O[b][half][0][0];
    #pragma unroll
    for (int ni = 0; ni < 16; ni++) {
        int c = ni * 8 + (ln & 3) * 2;
        *(float2*)(O0 + (size_t)r0 * CH + c) = make_float2(o[ni][0], o[ni][1]);
        *(float2*)(O0 + (size_t)r1 * CH + c) = make_float2(o[ni][2], o[ni][3]);
    }
    if ((ln & 3) == 0) {
        g_ms[b][half][r0] = rm0; g_ls[b][half][r0] = rl0;
        g_ms[b][half][r1] = rm1; g_ls[b][half][r1] = rl1;
    }
}

// ---------------- K5: LSE combine, transpose, residual ----------------
__global__ __launch_bounds__(256) void k5_reduce(
    const float* __restrict__ x, const float* __restrict__ gamma,
    float* __restrict__ out)
{
    const int n0 = blockIdx.x * 32;
    const int b  = blockIdx.y;
    const int t  = threadIdx.x;
    const float g = *gamma;

    __shared__ float s[128][33];
    __shared__ float f0[32], f1[32];

    if (t < 32) {
        int n = n0 + t;
        float m1 = g_ms[b][0][n], l1 = g_ls[b][0][n];
        float m2 = g_ms[b][1][n], l2 = g_ls[b][1][n];
        float M  = fmaxf(m1, m2);
        float w1 = __expf(m1 - M), w2 = __expf(m2 - M);
        float inv = 1.0f / (w1 * l1 + w2 * l2);
        f0[t] = w1 * inv; f1[t] = w2 * inv;
    }
    __syncthreads();

    for (int i = t; i < 32 * 128; i += 256) {
        int nl = i >> 7, c = i & 127;
        s[c][nl] = f0[nl] * g_O[b][0][n0 + nl][c] + f1[nl] * g_O[b][1][n0 + nl][c];
    }
    __syncthreads();
    const size_t base = (size_t)b * CH * NTOK;
    for (int i = t; i < 128 * 32; i += 256) {
        int c = i >> 5, nl = i & 31;
        size_t idx = base + (size_t)c * NTOK + n0 + nl;
        out[idx] = x[idx] + g * s[c][nl];
    }
}

extern "C" void kernel_launch(void* const* d_in, const int* in_sizes, int n_in,
                              void* d_out, int out_size) {
    const float* x  = (const float*)d_in[0];
    const float* Wq = (const float*)d_in[1];
    const float* bq = (const float*)d_in[2];
    const float* Wk = (const float*)d_in[3];
    const float* bk = (const float*)d_in[4];
    const float* Wv = (const float*)d_in[5];
    const float* bv = (const float*)d_in[6];
    const float* gm = (const float*)d_in[7];
    float* out = (float*)d_out;

    cudaFuncSetAttribute(k2_attn, cudaFuncAttributeMaxDynamicSharedMemorySize,
                         (int)sizeof(SmemT));

    k1_proj  <<<dim3(NTOK / 64, 3, BATCH), 256>>>(x, Wq, bq, Wk, bk, Wv, bv);
    k2_attn  <<<dim3(NTOK / 128, 2, BATCH), 256, sizeof(SmemT)>>>();
    k5_reduce<<<dim3(NTOK / 32, BATCH),     256>>>(x, gm, out);
}

// round 15
// speedup vs baseline: 1.4568x; 1.0011x over previous
#include <cuda_runtime.h>
#include <cuda_bf16.h>
#include <cstdint>

#define BATCH 2
#define CH    128
#define NTOK  4096
#define KT    64
#define HALF_M 2048
#define NTILES 32

// ---------------- scratch (device .bss — no allocation) ----------------
__device__ __nv_bfloat16 g_qh[BATCH][NTOK][CH];   // q pre-scaled by 1.3
__device__ __nv_bfloat16 g_ql[BATCH][NTOK][CH];
__device__ __nv_bfloat16 g_kh[BATCH][NTOK][CH];
__device__ __nv_bfloat16 g_kl[BATCH][NTOK][CH];
__device__ __nv_bfloat16 g_v [BATCH][CH][NTOK];
__device__ float g_O [BATCH][2][NTOK][CH];
__device__ float g_ms[BATCH][2][NTOK];
__device__ float g_ls[BATCH][2][NTOK];

// ---------------- smem for fused attention ----------------
struct SmemT {
    __nv_bfloat16 kh[2][64][136];
    __nv_bfloat16 kl[2][64][136];
    __nv_bfloat16 v [2][128][72];
};

// ---------------- helpers ----------------
__device__ __forceinline__ void ldsm4(uint32_t r[4], const void* p) {
    uint32_t a = (uint32_t)__cvta_generic_to_shared(p);
    asm volatile("ldmatrix.sync.aligned.m8n8.x4.shared.b16 {%0,%1,%2,%3}, [%4];\n"
                 : "=r"(r[0]), "=r"(r[1]), "=r"(r[2]), "=r"(r[3]) : "r"(a));
}
__device__ __forceinline__ void mma_bf16(float c[4], const uint32_t a[4], uint32_t b0, uint32_t b1) {
    asm volatile("mma.sync.aligned.m16n8k16.row.col.f32.bf16.bf16.f32 "
                 "{%0,%1,%2,%3},{%4,%5,%6,%7},{%8,%9},{%0,%1,%2,%3};\n"
                 : "+f"(c[0]), "+f"(c[1]), "+f"(c[2]), "+f"(c[3])
                 : "r"(a[0]), "r"(a[1]), "r"(a[2]), "r"(a[3]), "r"(b0), "r"(b1));
}
__device__ __forceinline__ void cpa16(void* dst, const void* src) {
    uint32_t d = (uint32_t)__cvta_generic_to_shared(dst);
    asm volatile("cp.async.cg.shared.global [%0], [%1], 16;\n" :: "r"(d), "l"(src));
}
#define CP_COMMIT() asm volatile("cp.async.commit_group;\n")
#define CP_WAIT(n)  asm volatile("cp.async.wait_group %0;\n" :: "n"(n))

__device__ __forceinline__ void issue_tile(SmemT* sm, int b, int half, int tt, int st, int tid) {
    const int m0 = half * HALF_M + tt * KT;
    #pragma unroll
    for (int i = tid; i < 3072; i += 256) {
        if (i < 1024) {
            int r = i >> 4, ch = i & 15;
            cpa16(&sm->kh[st][r][ch * 8], &g_kh[b][m0 + r][ch * 8]);
        } else if (i < 2048) {
            int j = i - 1024, r = j >> 4, ch = j & 15;
            cpa16(&sm->kl[st][r][ch * 8], &g_kl[b][m0 + r][ch * 8]);
        } else {
            int j = i - 2048, r = j >> 3, ch = j & 7;
            cpa16(&sm->v[st][r][ch * 8], &g_v[b][r][m0 + ch * 8]);
        }
    }
}

// ---------------- K1: QKV projection (fp32), n-tile 64, 384 CTAs ----------------
__global__ __launch_bounds__(256) void k1_proj(
    const float* __restrict__ x,
    const float* __restrict__ Wq, const float* __restrict__ bq,
    const float* __restrict__ Wk, const float* __restrict__ bk,
    const float* __restrict__ Wv, const float* __restrict__ bv)
{
    const int n0  = blockIdx.x * 64;
    const int mat = blockIdx.y;
    const int b   = blockIdx.z;
    const float* W    = (mat == 0) ? Wq : (mat == 1) ? Wk : Wv;
    const float* bias = (mat == 0) ? bq : (mat == 1) ? bk : bv;

    __shared__ float sW[32][132];   // [c-local][o], transposed, padded
    __shared__ float sX[32][64];    // [c-local][n-local]

    const int t  = threadIdx.x;
    const int n4 = (t & 15) * 4;    // 16 groups x 4 n = 64 n
    const int ob = (t >> 4) * 8;    // 16 groups x 8 o = 128 o

    float acc[8][4];
    #pragma unroll
    for (int i = 0; i < 8; i++)
        #pragma unroll
        for (int j = 0; j < 4; j++) acc[i][j] = 0.f;

    const float* xb = x + (size_t)b * CH * NTOK;

    for (int c0 = 0; c0 < 128; c0 += 32) {
        __syncthreads();
        for (int i = t; i < 128 * 8; i += 256) {
            int o = i >> 3, u = i & 7;
            float4 w4 = *(const float4*)(W + o * 128 + c0 + u * 4);
            sW[u * 4 + 0][o] = w4.x; sW[u * 4 + 1][o] = w4.y;
            sW[u * 4 + 2][o] = w4.z; sW[u * 4 + 3][o] = w4.w;
        }
        for (int i = t; i < 512; i += 256) {
            int r = i >> 4, u = i & 15;
            *(float4*)&sX[r][u * 4] = *(const float4*)(xb + (size_t)(c0 + r) * NTOK + n0 + u * 4);
        }
        __syncthreads();
        #pragma unroll
        for (int c = 0; c < 32; c++) {
            float4 xv = *(float4*)&sX[c][n4];
            #pragma unroll
            for (int iq = 0; iq < 2; iq++) {
                float4 wv = *(float4*)&sW[c][ob + iq * 4];
                float wr[4] = {wv.x, wv.y, wv.z, wv.w};
                #pragma unroll
                for (int jj = 0; jj < 4; jj++) {
                    acc[iq * 4 + jj][0] += wr[jj] * xv.x;
                    acc[iq * 4 + jj][1] += wr[jj] * xv.y;
                    acc[iq * 4 + jj][2] += wr[jj] * xv.z;
                    acc[iq * 4 + jj][3] += wr[jj] * xv.w;
                }
            }
        }
    }

    float bi[8];
    #pragma unroll
    for (int i = 0; i < 8; i++) bi[i] = bias[ob + i];
    const float scale = (mat == 0) ? 1.3f : 1.0f;   // fold logit scale into q

    if (mat == 2) {
        #pragma unroll
        for (int i = 0; i < 8; i++) {
            __align__(8) __nv_bfloat16 h[4];
            #pragma unroll
            for (int j = 0; j < 4; j++) h[j] = __float2bfloat16(acc[i][j] + bi[i]);
            *(uint2*)&g_v[b][ob + i][n0 + n4] = *(uint2*)h;
        }
    } else {
        __nv_bfloat16 (*dh)[NTOK][CH] = (mat == 0) ? g_qh : g_kh;
        __nv_bfloat16 (*dl)[NTOK][CH] = (mat == 0) ? g_ql : g_kl;
        #pragma unroll
        for (int j = 0; j < 4; j++) {
            __align__(16) __nv_bfloat16 hh[8];
            __align__(16) __nv_bfloat16 ll[8];
            #pragma unroll
            for (int i = 0; i < 8; i++) {
                float v = (acc[i][j] + bi[i]) * scale;
                __nv_bfloat16 h = __float2bfloat16(v);
                hh[i] = h;
                ll[i] = __float2bfloat16(v - __bfloat162float(h));
            }
            int n = n0 + n4 + j;
            *(uint4*)&dh[b][n][ob] = *(uint4*)&hh[0];
            *(uint4*)&dl[b][n][ob] = *(uint4*)&ll[0];
        }
    }
}

// ---------------- K2: fused flash attention (split-K=2 over kv) ----------------
__global__ __launch_bounds__(256, 1) void k2_attn() {
    extern __shared__ char smem_raw[];
    SmemT* sm = (SmemT*)smem_raw;

    const int n0   = blockIdx.x * 128;
    const int half = blockIdx.y;
    const int b    = blockIdx.z;
    const int t    = threadIdx.x, wid = t >> 5, ln = t & 31;

    // ---- load Q fragments (hi/lo) into registers, staged through smem ----
    uint32_t qh[8][4], ql[8][4];
    for (int round = 0; round < 2; round++) {
        for (int i = t; i < 1024; i += 256) {
            int r = i >> 4, ch = i & 15;
            *(uint4*)&sm->kh[0][r][ch * 8] = *(const uint4*)&g_qh[b][n0 + round * 64 + r][ch * 8];
            *(uint4*)&sm->kl[0][r][ch * 8] = *(const uint4*)&g_ql[b][n0 + round * 64 + r][ch * 8];
        }
        __syncthreads();
        if ((wid >> 2) == round) {
            int wl = (wid & 3) * 16;
            #pragma unroll
            for (int ks = 0; ks < 8; ks++) {
                ldsm4(qh[ks], &sm->kh[0][wl + (ln & 15)][ks * 16 + (ln >> 4) * 8]);
                ldsm4(ql[ks], &sm->kl[0][wl + (ln & 15)][ks * 16 + (ln >> 4) * 8]);
            }
        }
        __syncthreads();
    }

    float o[16][4];
    #pragma unroll
    for (int i = 0; i < 16; i++)
        #pragma unroll
        for (int j = 0; j < 4; j++) o[i][j] = 0.f;
    float rm0 = -1e30f, rm1 = -1e30f, rl0 = 0.f, rl1 = 0.f;

    issue_tile(sm, b, half, 0, 0, t);
    CP_COMMIT();

    for (int tt = 0; tt < NTILES; tt++) {
        const int st = tt & 1;
        if (tt + 1 < NTILES) {
            issue_tile(sm, b, half, tt + 1, (tt + 1) & 1, t);
            CP_COMMIT();
            CP_WAIT(1);
        } else {
            CP_WAIT(0);
        }
        __syncthreads();

        // ---- S = qh·kh + qh·kl + ql·kh  (q pre-scaled by 1.3) ----
        float s[8][4];
        #pragma unroll
        for (int i = 0; i < 8; i++)
            #pragma unroll
            for (int j = 0; j < 4; j++) s[i][j] = 0.f;

        #pragma unroll
        for (int ks = 0; ks < 8; ks++) {
            const int kk = ks * 16;
            uint32_t bh[4][4], bl[4][4];
            #pragma unroll
            for (int g = 0; g < 4; g++) {
                int rr = g * 16 + (ln & 7) + ((ln >> 4) << 3);
                int cc = kk + (((ln >> 3) & 1) << 3);
                ldsm4(bh[g], &sm->kh[st][rr][cc]);
                ldsm4(bl[g], &sm->kl[st][rr][cc]);
            }
            #pragma unroll
            for (int g = 0; g < 4; g++)
                #pragma unroll
                for (int j = 0; j < 2; j++) {
                    const int ni = g * 2 + j;
                    mma_bf16(s[ni], qh[ks], bh[g][j * 2], bh[g][j * 2 + 1]);
                    mma_bf16(s[ni], qh[ks], bl[g][j * 2], bl[g][j * 2 + 1]);
                    mma_bf16(s[ni], ql[ks], bh[g][j * 2], bh[g][j * 2 + 1]);
                }
        }

        // ---- online softmax ----
        float tm0 = -1e30f, tm1 = -1e30f;
        #pragma unroll
        for (int i = 0; i < 8; i++) {
            tm0 = fmaxf(tm0, fmaxf(s[i][0], s[i][1]));
            tm1 = fmaxf(tm1, fmaxf(s[i][2], s[i][3]));
        }
        tm0 = fmaxf(tm0, __shfl_xor_sync(0xffffffffu, tm0, 1));
        tm0 = fmaxf(tm0, __shfl_xor_sync(0xffffffffu, tm0, 2));
        tm1 = fmaxf(tm1, __shfl_xor_sync(0xffffffffu, tm1, 1));
        tm1 = fmaxf(tm1, __shfl_xor_sync(0xffffffffu, tm1, 2));

        const float mn0 = fmaxf(rm0, tm0), mn1 = fmaxf(rm1, tm1);
        const float sc0 = __expf(rm0 - mn0), sc1 = __expf(rm1 - mn1);
        rm0 = mn0; rm1 = mn1;

        float ts0 = 0.f, ts1 = 0.f;
        #pragma unroll
        for (int i = 0; i < 8; i++) {
            s[i][0] = __expf(s[i][0] - mn0);
            s[i][1] = __expf(s[i][1] - mn0);
            s[i][2] = __expf(s[i][2] - mn1);
            s[i][3] = __expf(s[i][3] - mn1);
            ts0 += s[i][0] + s[i][1];
            ts1 += s[i][2] + s[i][3];
        }
        ts0 += __shfl_xor_sync(0xffffffffu, ts0, 1);
        ts0 += __shfl_xor_sync(0xffffffffu, ts0, 2);
        ts1 += __shfl_xor_sync(0xffffffffu, ts1, 1);
        ts1 += __shfl_xor_sync(0xffffffffu, ts1, 2);
        rl0 = rl0 * sc0 + ts0;
        rl1 = rl1 * sc1 + ts1;

        #pragma unroll
        for (int i = 0; i < 16; i++) {
            o[i][0] *= sc0; o[i][1] *= sc0;
            o[i][2] *= sc1; o[i][3] *= sc1;
        }

        // ---- repack P (C-frag -> A-frag) ----
        uint32_t pf[4][4];
        #pragma unroll
        for (int kp = 0; kp < 4; kp++) {
            __nv_bfloat162 h;
            h = __floats2bfloat162_rn(s[2*kp][0],   s[2*kp][1]);   pf[kp][0] = *(uint32_t*)&h;
            h = __floats2bfloat162_rn(s[2*kp][2],   s[2*kp][3]);   pf[kp][1] = *(uint32_t*)&h;
            h = __floats2bfloat162_rn(s[2*kp+1][0], s[2*kp+1][1]); pf[kp][2] = *(uint32_t*)&h;
            h = __floats2bfloat162_rn(s[2*kp+1][2], s[2*kp+1][3]); pf[kp][3] = *(uint32_t*)&h;
        }

        // ---- O += P · V^T ----
        #pragma unroll
        for (int kp = 0; kp < 4; kp++) {
            #pragma unroll
            for (int cg = 0; cg < 8; cg++) {
                uint32_t vb[4];
                ldsm4(vb, &sm->v[st][cg * 16 + (ln & 7) + ((ln >> 4) << 3)]
                                    [kp * 16 + (((ln >> 3) & 1) << 3)]);
                mma_bf16(o[cg * 2],     pf[kp], vb[0], vb[1]);
                mma_bf16(o[cg * 2 + 1], pf[kp], vb[2], vb[3]);
            }
        }
        __syncthreads();
    }

    // ---- epilogue: unnormalized O + row stats ----
    const int gr = ln >> 2;
    const int r0 = n0 + wid * 16 + gr, r1 = r0 + 8;
    float* O0 = &g_O[b][half][0][0];
    #pragma unroll
    for (int ni = 0; ni < 16; ni++) {
        int c = ni * 8 + (ln & 3) * 2;
        *(float2*)(O0 + (size_t)r0 * CH + c) = make_float2(o[ni][0], o[ni][1]);
        *(float2*)(O0 + (size_t)r1 * CH + c) = make_float2(o[ni][2], o[ni][3]);
    }
    if ((ln & 3) == 0) {
        g_ms[b][half][r0] = rm0; g_ls[b][half][r0] = rl0;
        g_ms[b][half][r1] = rm1; g_ls[b][half][r1] = rl1;
    }
}

// ---------------- K5: LSE combine, transpose, residual ----------------
__global__ __launch_bounds__(256) void k5_reduce(
    const float* __restrict__ x, const float* __restrict__ gamma,
    float* __restrict__ out)
{
    const int n0 = blockIdx.x * 32;
    const int b  = blockIdx.y;
    const int t  = threadIdx.x;
    const float g = *gamma;

    __shared__ float s[128][33];
    __shared__ float f0[32], f1[32];

    if (t < 32) {
        int n = n0 + t;
        float m1 = g_ms[b][0][n], l1 = g_ls[b][0][n];
        float m2 = g_ms[b][1][n], l2 = g_ls[b][1][n];
        float M  = fmaxf(m1, m2);
        float w1 = __expf(m1 - M), w2 = __expf(m2 - M);
        float inv = 1.0f / (w1 * l1 + w2 * l2);
        f0[t] = w1 * inv; f1[t] = w2 * inv;
    }
    __syncthreads();

    for (int i = t; i < 32 * 128; i += 256) {
        int nl = i >> 7, c = i & 127;
        s[c][nl] = f0[nl] * g_O[b][0][n0 + nl][c] + f1[nl] * g_O[b][1][n0 + nl][c];
    }
    __syncthreads();
    const size_t base = (size_t)b * CH * NTOK;
    for (int i = t; i < 128 * 32; i += 256) {
        int c = i >> 5, nl = i & 31;
        size_t idx = base + (size_t)c * NTOK + n0 + nl;
        out[idx] = x[idx] + g * s[c][nl];
    }
}

extern "C" void kernel_launch(void* const* d_in, const int* in_sizes, int n_in,
                              void* d_out, int out_size) {
    const float* x  = (const float*)d_in[0];
    const float* Wq = (const float*)d_in[1];
    const float* bq = (const float*)d_in[2];
    const float* Wk = (const float*)d_in[3];
    const float* bk = (const float*)d_in[4];
    const float* Wv = (const float*)d_in[5];
    const float* bv = (const float*)d_in[6];
    const float* gm = (const float*)d_in[7];
    float* out = (float*)d_out;

    cudaFuncSetAttribute(k2_attn, cudaFuncAttributeMaxDynamicSharedMemorySize,
                         (int)sizeof(SmemT));

    k1_proj  <<<dim3(NTOK / 64, 3, BATCH), 256>>>(x, Wq, bq, Wk, bk, Wv, bv);
    k2_attn  <<<dim3(NTOK / 128, 2, BATCH), 256, sizeof(SmemT)>>>();
    k5_reduce<<<dim3(NTOK / 32, BATCH),     256>>>(x, gm, out);
}